// round 1
// baseline (speedup 1.0000x reference)
#include <cuda_runtime.h>
#include <cstddef>

// Problem constants
namespace {
constexpr int kB  = 64;
constexpr int kN  = 64;
constexpr int kC  = 8;
constexpr int kF  = 256;
constexpr int kOC = 8;
constexpr int kOF = 256;
constexpr int kO  = kOC * kOF;   // 2048
constexpr int kCF = kC * kF;     // 2048
constexpr int kBN = kB * kN;     // 4096
}

// Scratch (device globals; no allocation allowed)
__device__ float g_w1sum[kF];
__device__ float g_w2sum[kF];
__device__ float g_s1[kB];
__device__ float g_w[kBN];
__device__ float g_t[kB * kCF];
__device__ float g_zx[kB * kCF];
__device__ float g_adj[(size_t)kB * kC * kF * kF];   // 134 MB
__device__ float g_zn[(size_t)kBN * kCF];            // 134 MB

// ---------------------------------------------------------------------------
// FFMA-pipe math helpers (avoid MUFU throughput wall: 33.5M sqrts + 4.2M rcps)
// ---------------------------------------------------------------------------
__device__ __forceinline__ float fast_rcp(float x) {
    // valid for x > 0 (we only use it on norm + 1e-7)
    float r = __uint_as_float(0x7ef311c3u - __float_as_uint(x));
    r = r * (2.0f - x * r);
    r = r * (2.0f - x * r);
    r = r * (2.0f - x * r);
    return r;
}

__device__ __forceinline__ float sgnroot(float a) {
    // sign(a) * sqrt(max(|a|, 1e-8)), with sign(0) == 0
    float x = fmaxf(fabsf(a), 1e-8f);
    float r = __uint_as_float(0x5f375a86u - (__float_as_uint(x) >> 1));
    r = r * (1.5f - 0.5f * x * r * r);
    r = r * (1.5f - 0.5f * x * r * r);
    r = r * (1.5f - 0.5f * x * r * r);
    float s = x * r;   // sqrt(x), rel err ~1e-7
    return (a == 0.0f) ? 0.0f : copysignf(s, a);
}

__device__ __forceinline__ float block_reduce_256(float v) {
    __shared__ float sh[8];
    int lane = threadIdx.x & 31, w = threadIdx.x >> 5;
    #pragma unroll
    for (int o = 16; o; o >>= 1) v += __shfl_xor_sync(0xffffffffu, v, o);
    if (lane == 0) sh[w] = v;
    __syncthreads();
    v = (threadIdx.x < 8) ? sh[threadIdx.x] : 0.0f;
    if (w == 0) {
        #pragma unroll
        for (int o = 4; o; o >>= 1) v += __shfl_xor_sync(0xffffffffu, v, o);
    }
    return v;   // valid on warp 0
}

// ---------------------------------------------------------------------------
// K0: column sums of W1 / W2 (the 'kf->' part of the einsums)
// ---------------------------------------------------------------------------
__global__ void k_wsum(const float* __restrict__ W1, const float* __restrict__ W2) {
    int f = threadIdx.x;
    float s1 = 0.f, s2 = 0.f;
    #pragma unroll
    for (int c = 0; c < kC; c++) {
        s1 += W1[c * kF + f];
        s2 += W2[c * kF + f];
    }
    g_w1sum[f] = s1;
    g_w2sum[f] = s2;
}

// K1: s1[b] = sum_{c,f} x[b,c,f] * w1sum[f]
__global__ void k_s1(const float* __restrict__ x) {
    int b = blockIdx.x;
    float acc = 0.f;
    const float* p = x + (size_t)b * kCF;
    for (int i = threadIdx.x; i < kCF; i += 256)
        acc = fmaf(p[i], g_w1sum[i & (kF - 1)], acc);
    acc = block_reduce_256(acc);
    if (threadIdx.x == 0) g_s1[b] = acc;
}

// K2: w[b,n] = s1[b] * (sum_{c,f} nb[b,n,c,f] * w2sum[f])
__global__ void k_w(const float* __restrict__ nb) {
    int bn = blockIdx.x;
    float acc = 0.f;
    const float* p = nb + (size_t)bn * kCF;
    for (int i = threadIdx.x; i < kCF; i += 256)
        acc = fmaf(p[i], g_w2sum[i & (kF - 1)], acc);
    acc = block_reduce_256(acc);
    if (threadIdx.x == 0) g_w[bn] = g_s1[bn >> 6] * acc;
}

// K3: t[b,c,f] = sum_n w[b,n] * nb[b,n,c,f]
__global__ void k_t(const float* __restrict__ nb) {
    int bc = blockIdx.x;
    int b = bc >> 3, c = bc & 7;
    __shared__ float ws[kN];
    if (threadIdx.x < kN) ws[threadIdx.x] = g_w[b * kN + threadIdx.x];
    __syncthreads();
    int f = threadIdx.x;
    const float* p = nb + ((size_t)b * kN) * kCF + c * kF + f;
    float acc = 0.f;
    #pragma unroll 8
    for (int n = 0; n < kN; n++) acc = fmaf(ws[n], p[(size_t)n * kCF], acc);
    g_t[(size_t)bc * kF + f] = acc;
}

// ---------------------------------------------------------------------------
// K4: adj[b,c,a,d] = row_normalize_c( sgnroot( x[c,a]t[c,d] + x[c,d]t[c,a] ) )
// grid: (16 a-tiles, B), 256 threads = d
// ---------------------------------------------------------------------------
__global__ void __launch_bounds__(256) k_adj(const float* __restrict__ x) {
    int b = blockIdx.y;
    int at = blockIdx.x;   // tile of 16 'a' values
    __shared__ float xs[kCF];
    __shared__ float ts[kCF];
    for (int i = threadIdx.x; i < kCF; i += 256) {
        xs[i] = x[(size_t)b * kCF + i];
        ts[i] = g_t[(size_t)b * kCF + i];
    }
    __syncthreads();
    int d = threadIdx.x;
    float xd[kC], td[kC];
    #pragma unroll
    for (int c = 0; c < kC; c++) { xd[c] = xs[c * kF + d]; td[c] = ts[c * kF + d]; }

    for (int ai = 0; ai < 16; ai++) {
        int a = at * 16 + ai;
        float v[kC];
        float norm = 0.f;
        #pragma unroll
        for (int c = 0; c < kC; c++) {
            float va = xs[c * kF + a] * td[c] + xd[c] * ts[c * kF + a];
            float sv = sgnroot(va);
            v[c] = sv;
            norm += fabsf(sv);
        }
        float inv = fast_rcp(norm + 1e-7f);
        #pragma unroll
        for (int c = 0; c < kC; c++)
            g_adj[((size_t)(b * kC + c) * kF + a) * kF + d] = v[c] * inv;
    }
}

// ---------------------------------------------------------------------------
// K5: zx[b,c,a] = sum_d adj[b,c,a,d] * x[b,c,d]
// block = (bc, 8-a chunk); 8 warps, one 'a' per warp
// ---------------------------------------------------------------------------
__global__ void k_zx(const float* __restrict__ x) {
    int blk = blockIdx.x;
    int a8 = blk & 31, bc = blk >> 5;
    int warp = threadIdx.x >> 5, lane = threadIdx.x & 31;
    int a = a8 * 8 + warp;
    const float* adjrow = g_adj + ((size_t)bc * kF + a) * kF;
    const float* xr = x + (size_t)bc * kF;
    float acc = 0.f;
    #pragma unroll
    for (int d = lane; d < kF; d += 32) acc = fmaf(adjrow[d], xr[d], acc);
    #pragma unroll
    for (int o = 16; o; o >>= 1) acc += __shfl_xor_sync(0xffffffffu, acc, o);
    if (lane == 0) g_zx[(size_t)bc * kF + a] = acc;
}

// ---------------------------------------------------------------------------
// K6: zn[b,n,c,a] = sum_d adj[b,c,a,d] * nb[b,n,c,d]
// one block per (b,c): 64x256 output, K=256, 256 threads, 8x8 register tiles
// ---------------------------------------------------------------------------
__global__ void __launch_bounds__(256) k_zn(const float* __restrict__ nb) {
    int bc = blockIdx.x;
    int b = bc >> 3, c = bc & 7;
    __shared__ float nbT[32][65];    // [d][n], padded
    __shared__ float adjT[32][257];  // [d][a], padded
    int tid = threadIdx.x;
    int tn = tid >> 5, ta = tid & 31;
    float acc[8][8];
    #pragma unroll
    for (int i = 0; i < 8; i++)
        #pragma unroll
        for (int j = 0; j < 8; j++) acc[i][j] = 0.f;

    const float* nb_bc = nb + ((size_t)b * kN) * kCF + c * kF;
    const float* adj_bc = g_adj + (size_t)bc * kF * kF;
    int dl = tid & 31, rl = tid >> 5;

    for (int d0 = 0; d0 < kF; d0 += 32) {
        #pragma unroll
        for (int r = 0; r < 8; r++) {
            int n = rl + 8 * r;
            nbT[dl][n] = nb_bc[(size_t)n * kCF + d0 + dl];
        }
        #pragma unroll
        for (int r = 0; r < 32; r++) {
            int a = rl + 8 * r;
            adjT[dl][a] = adj_bc[(size_t)a * kF + d0 + dl];
        }
        __syncthreads();
        #pragma unroll
        for (int dd = 0; dd < 32; dd++) {
            float bv[8];
            #pragma unroll
            for (int i = 0; i < 8; i++) bv[i] = nbT[dd][tn * 8 + i];
            #pragma unroll
            for (int j = 0; j < 8; j++) {
                float av = adjT[dd][ta + 32 * j];
                #pragma unroll
                for (int i = 0; i < 8; i++) acc[i][j] = fmaf(bv[i], av, acc[i][j]);
            }
        }
        __syncthreads();
    }
    #pragma unroll
    for (int i = 0; i < 8; i++) {
        int n = tn * 8 + i;
        float* dst = g_zn + ((size_t)(b * kN + n) * kC + c) * kF;
        #pragma unroll
        for (int j = 0; j < 8; j++) dst[ta + 32 * j] = acc[i][j];
    }
}

// ---------------------------------------------------------------------------
// K7: C[M,2048] = A[M,2048] @ Wc[2048,2048]^T   (both K-contiguous, NT GEMM)
// 128x128 tile, BK=16, 256 threads, 8x8 per thread.  sel: 1 -> zn, 0 -> zx
// ---------------------------------------------------------------------------
__global__ void __launch_bounds__(256) k_gemm(const float* __restrict__ Wc,
                                              float* __restrict__ Cm,
                                              int M, int sel) {
    const float* A = sel ? g_zn : g_zx;
    const int K = kCF;   // 2048
    __shared__ float As[16][132];
    __shared__ float Bs[16][132];
    int bm = blockIdx.y * 128, bn = blockIdx.x * 128;
    int tid = threadIdx.x;
    int tr = tid >> 4, tc = tid & 15;
    float acc[8][8];
    #pragma unroll
    for (int i = 0; i < 8; i++)
        #pragma unroll
        for (int j = 0; j < 8; j++) acc[i][j] = 0.f;

    for (int kk = 0; kk < K; kk += 16) {
        #pragma unroll
        for (int l = 0; l < 2; l++) {
            int f4 = tid + l * 256;        // 0..511
            int row = f4 >> 2;             // 0..127
            int c4 = (f4 & 3) << 2;        // 0,4,8,12
            float4 va = make_float4(0.f, 0.f, 0.f, 0.f);
            if (bm + row < M)
                va = *(const float4*)(A + (size_t)(bm + row) * K + kk + c4);
            As[c4 + 0][row] = va.x; As[c4 + 1][row] = va.y;
            As[c4 + 2][row] = va.z; As[c4 + 3][row] = va.w;
            float4 vb = *(const float4*)(Wc + (size_t)(bn + row) * K + kk + c4);
            Bs[c4 + 0][row] = vb.x; Bs[c4 + 1][row] = vb.y;
            Bs[c4 + 2][row] = vb.z; Bs[c4 + 3][row] = vb.w;
        }
        __syncthreads();
        #pragma unroll
        for (int k = 0; k < 16; k++) {
            float4 a0 = *(const float4*)&As[k][tr * 8];
            float4 a1 = *(const float4*)&As[k][tr * 8 + 4];
            float4 b0 = *(const float4*)&Bs[k][tc * 8];
            float4 b1 = *(const float4*)&Bs[k][tc * 8 + 4];
            float a8[8] = {a0.x, a0.y, a0.z, a0.w, a1.x, a1.y, a1.z, a1.w};
            float b8[8] = {b0.x, b0.y, b0.z, b0.w, b1.x, b1.y, b1.z, b1.w};
            #pragma unroll
            for (int i = 0; i < 8; i++)
                #pragma unroll
                for (int j = 0; j < 8; j++)
                    acc[i][j] = fmaf(a8[i], b8[j], acc[i][j]);
        }
        __syncthreads();
    }
    #pragma unroll
    for (int i = 0; i < 8; i++) {
        int row = bm + tr * 8 + i;
        if (row < M) {
            float4 o0 = make_float4(acc[i][0], acc[i][1], acc[i][2], acc[i][3]);
            float4 o1 = make_float4(acc[i][4], acc[i][5], acc[i][6], acc[i][7]);
            *(float4*)(Cm + (size_t)row * kO + bn + tc * 8)     = o0;
            *(float4*)(Cm + (size_t)row * kO + bn + tc * 8 + 4) = o1;
        }
    }
}

// ---------------------------------------------------------------------------
extern "C" void kernel_launch(void* const* d_in, const int* in_sizes, int n_in,
                              void* d_out, int out_size) {
    const float* x  = (const float*)d_in[0];   // (B,C,F)
    const float* nb = (const float*)d_in[1];   // (B,N,C,F)
    const float* W1 = (const float*)d_in[2];   // (C,F)
    const float* W2 = (const float*)d_in[3];   // (C,F)
    const float* Wc = (const float*)d_in[4];   // (OC*OF, C, F)
    float* out = (float*)d_out;
    float* x_out = out;                        // (B, OC, OF) = 131072
    float* n_out = out + (size_t)kB * kO;      // (B, N, OC, OF)

    k_wsum<<<1, 256>>>(W1, W2);
    k_s1<<<kB, 256>>>(x);
    k_w<<<kBN, 256>>>(nb);
    k_t<<<kB * kC, 256>>>(nb);
    k_adj<<<dim3(16, kB), 256>>>(x);
    k_zx<<<kB * kC * 32, 256>>>(x);
    k_zn<<<kB * kC, 256>>>(nb);
    k_gemm<<<dim3(16, 32), 256>>>(Wc, n_out, kBN, 1);   // n_out: M=4096
    k_gemm<<<dim3(16, 1), 256>>>(Wc, x_out, kB, 0);     // x_out: M=64
}

// round 6
// speedup vs baseline: 2.6902x; 2.6902x over previous
#include <cuda_runtime.h>
#include <cuda_bf16.h>
#include <cstdint>
#include <cstddef>

// Problem constants
namespace {
constexpr int kB  = 64;
constexpr int kN  = 64;
constexpr int kC  = 8;
constexpr int kF  = 256;
constexpr int kO  = 2048;   // OC*OF
constexpr int kCF = 2048;   // C*F
constexpr int kBN = 4096;   // B*N
constexpr int kK3 = 6144;   // widened K: [hi2048 | lo2048 | hi2048]
constexpr int kMp = 4224;   // 4096 zn + 64 zx + 64 pad (M tile multiple of 128)
}

// Scratch (device globals; no allocation allowed)
__device__ float g_w1sum[kF];
__device__ float g_w2sum[kF];
__device__ float g_s1[kB];
__device__ float g_w[kBN];
__device__ float g_t[kB * kCF];
__device__ float g_adj[(size_t)kB * kC * kF * kF];        // 134 MB
__device__ __nv_bfloat16 g_A3[(size_t)kMp * kK3];         // 52 MB  (zn|zx: hi,lo,hi)
__device__ __nv_bfloat16 g_B3[(size_t)kO * kK3];          // 25 MB  (Wc:    hi,hi,lo)

// ---------------------------------------------------------------------------
// FFMA-pipe math helpers
// ---------------------------------------------------------------------------
__device__ __forceinline__ float fast_rcp(float x) {
    float r = __uint_as_float(0x7ef311c3u - __float_as_uint(x));
    r = r * (2.0f - x * r);
    r = r * (2.0f - x * r);
    r = r * (2.0f - x * r);
    return r;
}

__device__ __forceinline__ float sgnroot(float a) {
    float x = fmaxf(fabsf(a), 1e-8f);
    float r = __uint_as_float(0x5f375a86u - (__float_as_uint(x) >> 1));
    r = r * (1.5f - 0.5f * x * r * r);
    r = r * (1.5f - 0.5f * x * r * r);
    r = r * (1.5f - 0.5f * x * r * r);
    float s = x * r;
    return (a == 0.0f) ? 0.0f : copysignf(s, a);
}

__device__ __forceinline__ float block_reduce_256(float v) {
    __shared__ float sh[8];
    int lane = threadIdx.x & 31, w = threadIdx.x >> 5;
    #pragma unroll
    for (int o = 16; o; o >>= 1) v += __shfl_xor_sync(0xffffffffu, v, o);
    if (lane == 0) sh[w] = v;
    __syncthreads();
    v = (threadIdx.x < 8) ? sh[threadIdx.x] : 0.0f;
    if (w == 0) {
        #pragma unroll
        for (int o = 4; o; o >>= 1) v += __shfl_xor_sync(0xffffffffu, v, o);
    }
    return v;
}

// hi/lo split stores: A rows get (hi, lo, hi); B rows get (hi, hi, lo)
__device__ __forceinline__ void split_store_A(__nv_bfloat16* row, int cf, float v) {
    __nv_bfloat16 h = __float2bfloat16(v);
    __nv_bfloat16 l = __float2bfloat16(v - __bfloat162float(h));
    row[cf] = h; row[2048 + cf] = l; row[4096 + cf] = h;
}
__device__ __forceinline__ void split_store_B(__nv_bfloat16* row, int cf, float v) {
    __nv_bfloat16 h = __float2bfloat16(v);
    __nv_bfloat16 l = __float2bfloat16(v - __bfloat162float(h));
    row[cf] = h; row[2048 + cf] = h; row[4096 + cf] = l;
}

__device__ __forceinline__ uint32_t s2u(const void* p) {
    uint32_t a;
    asm("{ .reg .u64 t; cvta.to.shared.u64 t, %1; cvt.u32.u64 %0, t; }" : "=r"(a) : "l"(p));
    return a;
}

// ---------------------------------------------------------------------------
// K0: column sums of W1 / W2
// ---------------------------------------------------------------------------
__global__ void k_wsum(const float* __restrict__ W1, const float* __restrict__ W2) {
    int f = threadIdx.x;
    float s1 = 0.f, s2 = 0.f;
    #pragma unroll
    for (int c = 0; c < kC; c++) {
        s1 += W1[c * kF + f];
        s2 += W2[c * kF + f];
    }
    g_w1sum[f] = s1;
    g_w2sum[f] = s2;
}

// K1: s1[b]
__global__ void k_s1(const float* __restrict__ x) {
    int b = blockIdx.x;
    float acc = 0.f;
    const float* p = x + (size_t)b * kCF;
    for (int i = threadIdx.x; i < kCF; i += 256)
        acc = fmaf(p[i], g_w1sum[i & (kF - 1)], acc);
    acc = block_reduce_256(acc);
    if (threadIdx.x == 0) g_s1[b] = acc;
}

// K2: w[b,n]
__global__ void k_w(const float* __restrict__ nb) {
    int bn = blockIdx.x;
    float acc = 0.f;
    const float* p = nb + (size_t)bn * kCF;
    for (int i = threadIdx.x; i < kCF; i += 256)
        acc = fmaf(p[i], g_w2sum[i & (kF - 1)], acc);
    acc = block_reduce_256(acc);
    if (threadIdx.x == 0) g_w[bn] = g_s1[bn >> 6] * acc;
}

// K3: t[b,c,f]
__global__ void k_t(const float* __restrict__ nb) {
    int bc = blockIdx.x;
    int b = bc >> 3, c = bc & 7;
    __shared__ float ws[kN];
    if (threadIdx.x < kN) ws[threadIdx.x] = g_w[b * kN + threadIdx.x];
    __syncthreads();
    int f = threadIdx.x;
    const float* p = nb + ((size_t)b * kN) * kCF + c * kF + f;
    float acc = 0.f;
    #pragma unroll 8
    for (int n = 0; n < kN; n++) acc = fmaf(ws[n], p[(size_t)n * kCF], acc);
    g_t[(size_t)bc * kF + f] = acc;
}

// ---------------------------------------------------------------------------
// K4: adj
// ---------------------------------------------------------------------------
__global__ void __launch_bounds__(256) k_adj(const float* __restrict__ x) {
    int b = blockIdx.y;
    int at = blockIdx.x;
    __shared__ float xs[kCF];
    __shared__ float ts[kCF];
    for (int i = threadIdx.x; i < kCF; i += 256) {
        xs[i] = x[(size_t)b * kCF + i];
        ts[i] = g_t[(size_t)b * kCF + i];
    }
    __syncthreads();
    int d = threadIdx.x;
    float xd[kC], td[kC];
    #pragma unroll
    for (int c = 0; c < kC; c++) { xd[c] = xs[c * kF + d]; td[c] = ts[c * kF + d]; }

    for (int ai = 0; ai < 16; ai++) {
        int a = at * 16 + ai;
        float v[kC];
        float norm = 0.f;
        #pragma unroll
        for (int c = 0; c < kC; c++) {
            float va = xs[c * kF + a] * td[c] + xd[c] * ts[c * kF + a];
            float sv = sgnroot(va);
            v[c] = sv;
            norm += fabsf(sv);
        }
        float inv = fast_rcp(norm + 1e-7f);
        #pragma unroll
        for (int c = 0; c < kC; c++)
            g_adj[((size_t)(b * kC + c) * kF + a) * kF + d] = v[c] * inv;
    }
}

// ---------------------------------------------------------------------------
// K5: zx -> A3 rows [4096, 4160)
// ---------------------------------------------------------------------------
__global__ void k_zx(const float* __restrict__ x) {
    int blk = blockIdx.x;
    int a8 = blk & 31, bc = blk >> 5;
    int warp = threadIdx.x >> 5, lane = threadIdx.x & 31;
    int a = a8 * 8 + warp;
    const float* adjrow = g_adj + ((size_t)bc * kF + a) * kF;
    const float* xr = x + (size_t)bc * kF;
    float acc = 0.f;
    #pragma unroll
    for (int d = lane; d < kF; d += 32) acc = fmaf(adjrow[d], xr[d], acc);
    #pragma unroll
    for (int o = 16; o; o >>= 1) acc += __shfl_xor_sync(0xffffffffu, acc, o);
    if (lane == 0) {
        int b = bc >> 3, c = bc & 7;
        split_store_A(g_A3 + (size_t)(4096 + b) * kK3, c * kF + a, acc);
    }
}

// ---------------------------------------------------------------------------
// K6: zn -> A3 rows [0, 4096)
// ---------------------------------------------------------------------------
__global__ void __launch_bounds__(256) k_zn(const float* __restrict__ nb) {
    int bc = blockIdx.x;
    int b = bc >> 3, c = bc & 7;
    __shared__ float nbT[32][65];
    __shared__ float adjT[32][257];
    int tid = threadIdx.x;
    int tn = tid >> 5, ta = tid & 31;
    float acc[8][8];
    #pragma unroll
    for (int i = 0; i < 8; i++)
        #pragma unroll
        for (int j = 0; j < 8; j++) acc[i][j] = 0.f;

    const float* nb_bc = nb + ((size_t)b * kN) * kCF + c * kF;
    const float* adj_bc = g_adj + (size_t)bc * kF * kF;
    int dl = tid & 31, rl = tid >> 5;

    for (int d0 = 0; d0 < kF; d0 += 32) {
        #pragma unroll
        for (int r = 0; r < 8; r++) {
            int n = rl + 8 * r;
            nbT[dl][n] = nb_bc[(size_t)n * kCF + d0 + dl];
        }
        #pragma unroll
        for (int r = 0; r < 32; r++) {
            int a = rl + 8 * r;
            adjT[dl][a] = adj_bc[(size_t)a * kF + d0 + dl];
        }
        __syncthreads();
        #pragma unroll
        for (int dd = 0; dd < 32; dd++) {
            float bv[8];
            #pragma unroll
            for (int i = 0; i < 8; i++) bv[i] = nbT[dd][tn * 8 + i];
            #pragma unroll
            for (int j = 0; j < 8; j++) {
                float av = adjT[dd][ta + 32 * j];
                #pragma unroll
                for (int i = 0; i < 8; i++) acc[i][j] = fmaf(bv[i], av, acc[i][j]);
            }
        }
        __syncthreads();
    }
    #pragma unroll
    for (int i = 0; i < 8; i++) {
        int n = tn * 8 + i;
        __nv_bfloat16* rowb = g_A3 + (size_t)(b * kN + n) * kK3;
        #pragma unroll
        for (int j = 0; j < 8; j++)
            split_store_A(rowb, c * kF + ta + 32 * j, acc[i][j]);
    }
}

// ---------------------------------------------------------------------------
// K7: Wc -> B3
// ---------------------------------------------------------------------------
__global__ void k_wconv(const float* __restrict__ Wc) {
    int o = blockIdx.x;
    __nv_bfloat16* rowb = g_B3 + (size_t)o * kK3;
    const float* src = Wc + (size_t)o * kCF;
    for (int j = threadIdx.x; j < kCF; j += 256)
        split_store_B(rowb, j, src[j]);
}

// ---------------------------------------------------------------------------
// K8: bf16 NT GEMM via mma.sync.m16n8k16 (HMMA — legal at compute_103)
// C[4224,2048] = A3[4224,6144] @ B3[2048,6144]^T
// CTA 128x128, BK=64 (128B rows, SW128 xor swizzle), 8 warps 4x2 (32x64 each),
// double-buffered cp.async.
// ---------------------------------------------------------------------------
namespace {
constexpr uint32_t kStage = 32768;   // A 16K + B 16K
constexpr uint32_t kSmemG = 2 * kStage;
}

__global__ void __launch_bounds__(256) k_mma(float* __restrict__ x_out,
                                             float* __restrict__ n_out) {
    extern __shared__ char sm[];
    int tid = threadIdx.x, lane = tid & 31, wid = tid >> 5;
    int wm = wid >> 1, wn = wid & 1;           // warp grid 4(m) x 2(n)
    int bm = blockIdx.y * 128, bn = blockIdx.x * 128;
    uint32_t sbase = s2u(sm);

    const char* Ag = (const char*)g_A3 + (size_t)bm * (kK3 * 2);
    const char* Bg = (const char*)g_B3 + (size_t)bn * (kK3 * 2);

    // cp.async stage loader: kk = element offset in K
    auto stage_load = [&](int kk, int s) {
        uint32_t base = sbase + (uint32_t)s * kStage;
        #pragma unroll
        for (int t = 0; t < 8; t++) {
            int u = tid + (t << 8);            // 0..2047 quads of 16B
            int isB = u >> 10;
            int v = u & 1023;
            int row = v >> 3, q = v & 7;
            const char* g = (isB ? Bg : Ag) + (size_t)row * (kK3 * 2) + kk * 2 + q * 16;
            uint32_t so = base + (uint32_t)isB * 16384u + (uint32_t)(row * 128)
                          + (uint32_t)((q * 16) ^ ((row & 7) << 4));
            asm volatile("cp.async.cg.shared.global [%0], [%1], 16;" :: "r"(so), "l"(g));
        }
        asm volatile("cp.async.commit_group;");
    };

    float acc[2][8][4];
    #pragma unroll
    for (int i = 0; i < 2; i++)
        #pragma unroll
        for (int j = 0; j < 8; j++)
            #pragma unroll
            for (int r = 0; r < 4; r++) acc[i][j][r] = 0.f;

    // precomputed per-lane ldmatrix row/byte components
    int aRow0 = wm * 32 + (lane & 15);                       // + mt*16
    int aKofs = (lane >> 4) << 4;
    int bRow0 = wn * 64 + (lane & 7) + ((lane & 16) >> 1);   // + nt*16
    int bKofs = (lane & 8) << 1;

    stage_load(0, 0);
    const int NIT = kK3 / 64;   // 96
    for (int it = 0; it < NIT; it++) {
        int s = it & 1;
        if (it + 1 < NIT) {
            stage_load((it + 1) * 64, (it + 1) & 1);
            asm volatile("cp.async.wait_group 1;");
        } else {
            asm volatile("cp.async.wait_group 0;");
        }
        __syncthreads();
        uint32_t aA = sbase + (uint32_t)s * kStage;
        uint32_t aB = aA + 16384u;
        #pragma unroll
        for (int k16 = 0; k16 < 4; k16++) {
            int kb = k16 * 32;
            uint32_t af[2][4];
            #pragma unroll
            for (int mt = 0; mt < 2; mt++) {
                int row = aRow0 + mt * 16;
                uint32_t ad = aA + row * 128 + ((kb + aKofs) ^ ((row & 7) << 4));
                asm volatile("ldmatrix.sync.aligned.m8n8.x4.shared.b16 {%0,%1,%2,%3}, [%4];"
                             : "=r"(af[mt][0]), "=r"(af[mt][1]), "=r"(af[mt][2]), "=r"(af[mt][3])
                             : "r"(ad));
            }
            uint32_t bf[4][4];
            #pragma unroll
            for (int nt = 0; nt < 4; nt++) {
                int row = bRow0 + nt * 16;
                uint32_t bd = aB + row * 128 + ((kb + bKofs) ^ ((row & 7) << 4));
                asm volatile("ldmatrix.sync.aligned.m8n8.x4.shared.b16 {%0,%1,%2,%3}, [%4];"
                             : "=r"(bf[nt][0]), "=r"(bf[nt][1]), "=r"(bf[nt][2]), "=r"(bf[nt][3])
                             : "r"(bd));
            }
            #pragma unroll
            for (int mt = 0; mt < 2; mt++)
                #pragma unroll
                for (int n8 = 0; n8 < 8; n8++) {
                    uint32_t b0 = bf[n8 >> 1][(n8 & 1) * 2 + 0];
                    uint32_t b1 = bf[n8 >> 1][(n8 & 1) * 2 + 1];
                    asm volatile(
                        "mma.sync.aligned.m16n8k16.row.col.f32.bf16.bf16.f32 "
                        "{%0,%1,%2,%3}, {%4,%5,%6,%7}, {%8,%9}, {%0,%1,%2,%3};"
                        : "+f"(acc[mt][n8][0]), "+f"(acc[mt][n8][1]),
                          "+f"(acc[mt][n8][2]), "+f"(acc[mt][n8][3])
                        : "r"(af[mt][0]), "r"(af[mt][1]), "r"(af[mt][2]), "r"(af[mt][3]),
                          "r"(b0), "r"(b1));
                }
        }
        __syncthreads();
    }

    // epilogue: direct fragment stores (guarded row split)
    int g = lane >> 2, tig = lane & 3;
    #pragma unroll
    for (int mt = 0; mt < 2; mt++) {
        #pragma unroll
        for (int half = 0; half < 2; half++) {
            int gm = bm + wm * 32 + mt * 16 + g + half * 8;
            if (gm < 4160) {
                float* dst = (gm < 4096)
                    ? n_out + (size_t)gm * kO
                    : x_out + (size_t)(gm - 4096) * kO;
                #pragma unroll
                for (int n8 = 0; n8 < 8; n8++) {
                    int col = bn + wn * 64 + n8 * 8 + tig * 2;
                    float2 v = half ? make_float2(acc[mt][n8][2], acc[mt][n8][3])
                                    : make_float2(acc[mt][n8][0], acc[mt][n8][1]);
                    *(float2*)(dst + col) = v;
                }
            }
        }
    }
}

// ---------------------------------------------------------------------------
extern "C" void kernel_launch(void* const* d_in, const int* in_sizes, int n_in,
                              void* d_out, int out_size) {
    const float* x  = (const float*)d_in[0];
    const float* nb = (const float*)d_in[1];
    const float* W1 = (const float*)d_in[2];
    const float* W2 = (const float*)d_in[3];
    const float* Wc = (const float*)d_in[4];
    float* out = (float*)d_out;
    float* x_out = out;                          // (B, OC, OF)
    float* n_out = out + (size_t)kB * kO;        // (B, N, OC, OF)

    cudaFuncSetAttribute(k_mma, cudaFuncAttributeMaxDynamicSharedMemorySize, kSmemG);

    k_wsum<<<1, 256>>>(W1, W2);
    k_s1<<<kB, 256>>>(x);
    k_w<<<kBN, 256>>>(nb);
    k_t<<<kB * kC, 256>>>(nb);
    k_adj<<<dim3(16, kB), 256>>>(x);
    k_zx<<<kB * kC * 32, 256>>>(x);
    k_zn<<<kB * kC, 256>>>(nb);
    k_wconv<<<kO, 256>>>(Wc);
    k_mma<<<dim3(16, 33), 256, kSmemG>>>(x_out, n_out);
}

// round 7
// speedup vs baseline: 3.7110x; 1.3794x over previous
#include <cuda_runtime.h>
#include <cuda_fp16.h>
#include <cstdint>
#include <cstddef>

// Problem constants
namespace {
constexpr int kB  = 64;
constexpr int kN  = 64;
constexpr int kC  = 8;
constexpr int kF  = 256;
constexpr int kO  = 2048;   // OC*OF
constexpr int kCF = 2048;   // C*F
constexpr int kBN = 4096;   // B*N
constexpr int kK2 = 4096;   // A operand widened K: [hi2048 | lo2048] fp16
constexpr int kMp = 4224;   // 4096 zn + 64 zx + 64 pad
}

// Scratch (device globals; no allocation allowed)
__device__ float g_w1sum[kF];
__device__ float g_w2sum[kF];
__device__ float g_s1[kB];
__device__ float g_w[kBN];
__device__ float g_t[kB * kCF];
__device__ __half g_adj2[(size_t)kB * kC * kF * 512];  // 134 MB: row(b,c,a)=[h256|l256]
__device__ __half g_A2[(size_t)kMp * kK2];             // 34.6 MB: row=[h2048|l2048]
__device__ __half g_B2h[(size_t)kO * kCF];             // 8.4 MB:  Wc fp16 hi

// ---------------------------------------------------------------------------
// FFMA-pipe math helpers
// ---------------------------------------------------------------------------
__device__ __forceinline__ float fast_rcp(float x) {
    float r = __uint_as_float(0x7ef311c3u - __float_as_uint(x));
    r = r * (2.0f - x * r);
    r = r * (2.0f - x * r);
    r = r * (2.0f - x * r);
    return r;
}

__device__ __forceinline__ float sgnroot(float a) {
    float x = fmaxf(fabsf(a), 1e-8f);
    float r = __uint_as_float(0x5f375a86u - (__float_as_uint(x) >> 1));
    r = r * (1.5f - 0.5f * x * r * r);
    r = r * (1.5f - 0.5f * x * r * r);
    r = r * (1.5f - 0.5f * x * r * r);
    float s = x * r;
    return (a == 0.0f) ? 0.0f : copysignf(s, a);
}

__device__ __forceinline__ float block_reduce_256(float v) {
    __shared__ float sh[8];
    int lane = threadIdx.x & 31, w = threadIdx.x >> 5;
    #pragma unroll
    for (int o = 16; o; o >>= 1) v += __shfl_xor_sync(0xffffffffu, v, o);
    if (lane == 0) sh[w] = v;
    __syncthreads();
    v = (threadIdx.x < 8) ? sh[threadIdx.x] : 0.0f;
    if (w == 0) {
        #pragma unroll
        for (int o = 4; o; o >>= 1) v += __shfl_xor_sync(0xffffffffu, v, o);
    }
    return v;
}

__device__ __forceinline__ uint32_t s2u(const void* p) {
    uint32_t a;
    asm("{ .reg .u64 t; cvta.to.shared.u64 t, %1; cvt.u32.u64 %0, t; }" : "=r"(a) : "l"(p));
    return a;
}

__device__ __forceinline__ uint32_t pack_h2(float a, float b) {
    __half ha = __float2half_rn(a), hb = __float2half_rn(b);
    return (uint32_t)__half_as_ushort(ha) | ((uint32_t)__half_as_ushort(hb) << 16);
}

// split store into g_A2 row: h at [cf], l at [2048+cf] (pairwise, cf even)
__device__ __forceinline__ void a2_store2(__half* row, int cf, float v0, float v1) {
    __half h0 = __float2half_rn(v0), h1 = __float2half_rn(v1);
    __half l0 = __float2half_rn(v0 - __half2float(h0));
    __half l1 = __float2half_rn(v1 - __half2float(h1));
    *(__half2*)(row + cf)        = __halves2half2(h0, h1);
    *(__half2*)(row + 2048 + cf) = __halves2half2(l0, l1);
}

// ---------------------------------------------------------------------------
// K0: column sums of W1 / W2
// ---------------------------------------------------------------------------
__global__ void k_wsum(const float* __restrict__ W1, const float* __restrict__ W2) {
    int f = threadIdx.x;
    float s1 = 0.f, s2 = 0.f;
    #pragma unroll
    for (int c = 0; c < kC; c++) {
        s1 += W1[c * kF + f];
        s2 += W2[c * kF + f];
    }
    g_w1sum[f] = s1;
    g_w2sum[f] = s2;
}

// K1: s1[b]
__global__ void k_s1(const float* __restrict__ x) {
    int b = blockIdx.x;
    float acc = 0.f;
    const float* p = x + (size_t)b * kCF;
    for (int i = threadIdx.x; i < kCF; i += 256)
        acc = fmaf(p[i], g_w1sum[i & (kF - 1)], acc);
    acc = block_reduce_256(acc);
    if (threadIdx.x == 0) g_s1[b] = acc;
}

// K2: w[b,n]
__global__ void k_w(const float* __restrict__ nb) {
    int bn = blockIdx.x;
    float acc = 0.f;
    const float* p = nb + (size_t)bn * kCF;
    for (int i = threadIdx.x; i < kCF; i += 256)
        acc = fmaf(p[i], g_w2sum[i & (kF - 1)], acc);
    acc = block_reduce_256(acc);
    if (threadIdx.x == 0) g_w[bn] = g_s1[bn >> 6] * acc;
}

// K3: t[b,c,f]
__global__ void k_t(const float* __restrict__ nb) {
    int bc = blockIdx.x;
    int b = bc >> 3, c = bc & 7;
    __shared__ float ws[kN];
    if (threadIdx.x < kN) ws[threadIdx.x] = g_w[b * kN + threadIdx.x];
    __syncthreads();
    int f = threadIdx.x;
    const float* p = nb + ((size_t)b * kN) * kCF + c * kF + f;
    float acc = 0.f;
    #pragma unroll 8
    for (int n = 0; n < kN; n++) acc = fmaf(ws[n], p[(size_t)n * kCF], acc);
    g_t[(size_t)bc * kF + f] = acc;
}

// ---------------------------------------------------------------------------
// K4: adj -> g_adj2 fp16 hi/lo rows  [b][c][a][h256 | l256]
// ---------------------------------------------------------------------------
__global__ void __launch_bounds__(256) k_adj(const float* __restrict__ x) {
    int b = blockIdx.y;
    int at = blockIdx.x;
    __shared__ float xs[kCF];
    __shared__ float ts[kCF];
    for (int i = threadIdx.x; i < kCF; i += 256) {
        xs[i] = x[(size_t)b * kCF + i];
        ts[i] = g_t[(size_t)b * kCF + i];
    }
    __syncthreads();
    int d = threadIdx.x;
    float xd[kC], td[kC];
    #pragma unroll
    for (int c = 0; c < kC; c++) { xd[c] = xs[c * kF + d]; td[c] = ts[c * kF + d]; }

    for (int ai = 0; ai < 16; ai++) {
        int a = at * 16 + ai;
        float v[kC];
        float norm = 0.f;
        #pragma unroll
        for (int c = 0; c < kC; c++) {
            float va = xs[c * kF + a] * td[c] + xd[c] * ts[c * kF + a];
            float sv = sgnroot(va);
            v[c] = sv;
            norm += fabsf(sv);
        }
        float inv = fast_rcp(norm + 1e-7f);
        #pragma unroll
        for (int c = 0; c < kC; c++) {
            float val = v[c] * inv;
            __half h = __float2half_rn(val);
            __half l = __float2half_rn(val - __half2float(h));
            __half* row = g_adj2 + ((size_t)(b * kC + c) * kF + a) * 512;
            row[d] = h;
            row[256 + d] = l;
        }
    }
}

// ---------------------------------------------------------------------------
// K5: zx -> g_A2 rows [4096, 4160)   (adj = h + l for accuracy)
// ---------------------------------------------------------------------------
__global__ void k_zx(const float* __restrict__ x) {
    int blk = blockIdx.x;
    int a8 = blk & 31, bc = blk >> 5;
    int warp = threadIdx.x >> 5, lane = threadIdx.x & 31;
    int a = a8 * 8 + warp;
    const __half* adjrow = g_adj2 + ((size_t)bc * kF + a) * 512;
    const float* xr = x + (size_t)bc * kF;
    float acc = 0.f;
    #pragma unroll
    for (int d = lane; d < kF; d += 32) {
        float av = __half2float(adjrow[d]) + __half2float(adjrow[256 + d]);
        acc = fmaf(av, xr[d], acc);
    }
    #pragma unroll
    for (int o = 16; o; o >>= 1) acc += __shfl_xor_sync(0xffffffffu, acc, o);
    if ((lane & 1) == 0) {
        // lane0 holds full sum; use lanes 0 of pairs? only lane 0 has it
    }
    if (lane == 0) {
        int b = bc >> 3, c = bc & 7;
        __half* row = g_A2 + (size_t)(4096 + b) * kK2;
        int cf = c * kF + a;
        __half h = __float2half_rn(acc);
        __half l = __float2half_rn(acc - __half2float(h));
        row[cf] = h;
        row[2048 + cf] = l;
    }
}

// ---------------------------------------------------------------------------
// K6: zn via HMMA: per (b,c)  C[64 n x 256 a] = NB[64 x 256 d] @ ADJ[256 x 256 d]^T
// fp16 3-term: [nh|nl|nh] . [ah|ah|al]  -> error ~2^-22
// smem: NB region 8 chunks x 8KB (h c0..3, l c0..3) = 64 KB (static),
//       ADJ double-buffered stages 2 x 32 KB.
// Writes zn straight into g_A2 in split-fp16 form.
// ---------------------------------------------------------------------------
namespace {
constexpr uint32_t kNbRegion = 65536;
constexpr uint32_t kAdjStage = 32768;
constexpr uint32_t kSmemZn   = kNbRegion + 2 * kAdjStage;  // 128 KB
}

__global__ void __launch_bounds__(256) k_zn_mma(const float* __restrict__ nb) {
    extern __shared__ char sm[];
    int tid = threadIdx.x, lane = tid & 31, wid = tid >> 5;
    int wm = wid >> 2, wn = wid & 3;             // 2(m) x 4(n); warp tile 32x64
    int bc = blockIdx.x;
    int b = bc >> 3, c = bc & 7;
    uint32_t sb = s2u(sm);
    uint32_t nbB = sb, adjB = sb + kNbRegion;

    const char* adj_bc = (const char*)(g_adj2 + (size_t)bc * kF * 512);  // row 1024 B
    const float* nb_bc = nb + ((size_t)b * kN) * kCF + c * kF;           // row stride kCF

    // term maps: A(NB) half: {h, l, h};  B(ADJ) half: {h, h, l}
    auto stage_load = [&](int it) {
        int t = it >> 2, q = it & 3;
        int srcoff = ((t == 2 ? 256 : 0) + q * 64) * 2;  // bytes within adj row
        uint32_t base = adjB + (uint32_t)(it & 1) * kAdjStage;
        #pragma unroll
        for (int k = 0; k < 8; k++) {
            int u = tid + (k << 8);          // 2048 quads: 256 rows x 8
            int row = u >> 3, q8 = u & 7;
            const char* g = adj_bc + (size_t)row * 1024 + srcoff + q8 * 16;
            uint32_t so = base + (uint32_t)(row * 128) + (uint32_t)((q8 * 16) ^ ((row & 7) << 4));
            asm volatile("cp.async.cg.shared.global [%0], [%1], 16;" :: "r"(so), "l"(g));
        }
        asm volatile("cp.async.commit_group;");
    };

    stage_load(0);

    // NB load + fp16 hi/lo split into smem chunks
    #pragma unroll
    for (int itc = 0; itc < 8; itc++) {
        int e = tid + (itc << 8);            // 2048 groups: 64 rows x 32 (8 d each)
        int row = e >> 5, d0 = (e & 31) << 3;
        float4 v0 = *(const float4*)(nb_bc + (size_t)row * kCF + d0);
        float4 v1 = *(const float4*)(nb_bc + (size_t)row * kCF + d0 + 4);
        float v[8] = {v0.x, v0.y, v0.z, v0.w, v1.x, v1.y, v1.z, v1.w};
        uint32_t hw[4], lw[4];
        #pragma unroll
        for (int j = 0; j < 4; j++) {
            float a0 = v[2 * j], a1 = v[2 * j + 1];
            __half h0 = __float2half_rn(a0), h1 = __float2half_rn(a1);
            float r0 = a0 - __half2float(h0), r1 = a1 - __half2float(h1);
            hw[j] = (uint32_t)__half_as_ushort(h0) | ((uint32_t)__half_as_ushort(h1) << 16);
            lw[j] = pack_h2(r0, r1);
        }
        int chunk = d0 >> 6, cw = d0 & 63;
        uint32_t off = (uint32_t)(chunk * 8192 + row * 128) + (uint32_t)((cw * 2) ^ ((row & 7) << 4));
        *(uint4*)(sm + off)         = make_uint4(hw[0], hw[1], hw[2], hw[3]);
        *(uint4*)(sm + 32768 + off) = make_uint4(lw[0], lw[1], lw[2], lw[3]);
    }

    float acc[2][8][4];
    #pragma unroll
    for (int i = 0; i < 2; i++)
        #pragma unroll
        for (int j = 0; j < 8; j++)
            #pragma unroll
            for (int r = 0; r < 4; r++) acc[i][j][r] = 0.f;

    int aRow0 = wm * 32 + (lane & 15);
    int aKofs = (lane >> 4) << 4;
    int bRow0 = wn * 64 + (lane & 7) + ((lane & 16) >> 1);
    int bKofs = (lane & 8) << 1;

    const int NIT = 12;
    for (int it = 0; it < NIT; it++) {
        if (it + 1 < NIT) {
            stage_load(it + 1);
            asm volatile("cp.async.wait_group 1;");
        } else {
            asm volatile("cp.async.wait_group 0;");
        }
        __syncthreads();
        int t = it >> 2, q = it & 3;
        int nbchunk = (t == 1 ? 4 : 0) + q;
        uint32_t aBase = nbB + (uint32_t)nbchunk * 8192u;
        uint32_t bBase = adjB + (uint32_t)(it & 1) * kAdjStage;
        #pragma unroll
        for (int k16 = 0; k16 < 4; k16++) {
            int kb = k16 * 32;
            uint32_t af[2][4];
            #pragma unroll
            for (int mt = 0; mt < 2; mt++) {
                int row = aRow0 + mt * 16;
                uint32_t ad = aBase + row * 128 + ((kb + aKofs) ^ ((row & 7) << 4));
                asm volatile("ldmatrix.sync.aligned.m8n8.x4.shared.b16 {%0,%1,%2,%3}, [%4];"
                             : "=r"(af[mt][0]), "=r"(af[mt][1]), "=r"(af[mt][2]), "=r"(af[mt][3])
                             : "r"(ad));
            }
            uint32_t bf[4][4];
            #pragma unroll
            for (int nt = 0; nt < 4; nt++) {
                int row = bRow0 + nt * 16;
                uint32_t bd = bBase + row * 128 + ((kb + bKofs) ^ ((row & 7) << 4));
                asm volatile("ldmatrix.sync.aligned.m8n8.x4.shared.b16 {%0,%1,%2,%3}, [%4];"
                             : "=r"(bf[nt][0]), "=r"(bf[nt][1]), "=r"(bf[nt][2]), "=r"(bf[nt][3])
                             : "r"(bd));
            }
            #pragma unroll
            for (int mt = 0; mt < 2; mt++)
                #pragma unroll
                for (int n8 = 0; n8 < 8; n8++) {
                    uint32_t b0 = bf[n8 >> 1][(n8 & 1) * 2 + 0];
                    uint32_t b1 = bf[n8 >> 1][(n8 & 1) * 2 + 1];
                    asm volatile(
                        "mma.sync.aligned.m16n8k16.row.col.f32.f16.f16.f32 "
                        "{%0,%1,%2,%3}, {%4,%5,%6,%7}, {%8,%9}, {%0,%1,%2,%3};"
                        : "+f"(acc[mt][n8][0]), "+f"(acc[mt][n8][1]),
                          "+f"(acc[mt][n8][2]), "+f"(acc[mt][n8][3])
                        : "r"(af[mt][0]), "r"(af[mt][1]), "r"(af[mt][2]), "r"(af[mt][3]),
                          "r"(b0), "r"(b1));
                }
        }
        __syncthreads();
    }

    // epilogue: split-fp16 store into g_A2 rows b*64 + n, cols c*256 + a
    int g = lane >> 2, tig = lane & 3;
    #pragma unroll
    for (int mt = 0; mt < 2; mt++) {
        #pragma unroll
        for (int half = 0; half < 2; half++) {
            int lr = wm * 32 + mt * 16 + g + half * 8;   // local n 0..63
            __half* dst = g_A2 + (size_t)(b * kN + lr) * kK2 + c * kF;
            #pragma unroll
            for (int n8 = 0; n8 < 8; n8++) {
                int col = wn * 64 + n8 * 8 + tig * 2;
                a2_store2(dst, col, acc[mt][n8][half * 2], acc[mt][n8][half * 2 + 1]);
            }
        }
    }
}

// ---------------------------------------------------------------------------
// K7: Wc -> g_B2h (fp16 hi only)
// ---------------------------------------------------------------------------
__global__ void k_wconv(const float* __restrict__ Wc) {
    int o = blockIdx.x;
    __half* rowb = g_B2h + (size_t)o * kCF;
    const float* src = Wc + (size_t)o * kCF;
    for (int j = threadIdx.x; j < kCF; j += 256)
        rowb[j] = __float2half_rn(src[j]);
}

// ---------------------------------------------------------------------------
// K8: fp16 2-term NT GEMM: C[4224,2048] = (Ah+Al)[4224,2048] @ Bh[2048,2048]^T
// K-loop: 64 chunks of 64 halves: it<32 -> Ah.Bh, it>=32 -> Al.Bh
// CTA 128x128, 8 warps 4x2, double-buffered cp.async.
// ---------------------------------------------------------------------------
namespace {
constexpr uint32_t kStage = 32768;   // A 16K + B 16K
constexpr uint32_t kSmemG = 2 * kStage;
}

__global__ void __launch_bounds__(256) k_mma2(float* __restrict__ x_out,
                                              float* __restrict__ n_out) {
    extern __shared__ char sm[];
    int tid = threadIdx.x, lane = tid & 31, wid = tid >> 5;
    int wm = wid >> 1, wn = wid & 1;             // 4(m) x 2(n)
    int bm = blockIdx.y * 128, bn = blockIdx.x * 128;
    uint32_t sbase = s2u(sm);

    const char* Ag = (const char*)(g_A2 + (size_t)bm * kK2);    // row 8192 B
    const char* Bg = (const char*)(g_B2h + (size_t)bn * kCF);   // row 4096 B

    auto stage_load = [&](int it) {
        int t = it >> 5, q = it & 31;
        int aoff = (t * 2048 + q * 64) * 2;
        int boff = (q * 64) * 2;
        uint32_t base = sbase + (uint32_t)(it & 1) * kStage;
        #pragma unroll
        for (int k = 0; k < 8; k++) {
            int u = tid + (k << 8);
            int isB = u >> 10;
            int v = u & 1023;
            int row = v >> 3, q8 = v & 7;
            const char* g = isB ? (Bg + (size_t)row * 4096 + boff + q8 * 16)
                                : (Ag + (size_t)row * 8192 + aoff + q8 * 16);
            uint32_t so = base + (uint32_t)isB * 16384u + (uint32_t)(row * 128)
                          + (uint32_t)((q8 * 16) ^ ((row & 7) << 4));
            asm volatile("cp.async.cg.shared.global [%0], [%1], 16;" :: "r"(so), "l"(g));
        }
        asm volatile("cp.async.commit_group;");
    };

    float acc[2][8][4];
    #pragma unroll
    for (int i = 0; i < 2; i++)
        #pragma unroll
        for (int j = 0; j < 8; j++)
            #pragma unroll
            for (int r = 0; r < 4; r++) acc[i][j][r] = 0.f;

    int aRow0 = wm * 32 + (lane & 15);
    int aKofs = (lane >> 4) << 4;
    int bRow0 = wn * 64 + (lane & 7) + ((lane & 16) >> 1);
    int bKofs = (lane & 8) << 1;

    stage_load(0);
    const int NIT = 64;
    for (int it = 0; it < NIT; it++) {
        int s = it & 1;
        if (it + 1 < NIT) {
            stage_load(it + 1);
            asm volatile("cp.async.wait_group 1;");
        } else {
            asm volatile("cp.async.wait_group 0;");
        }
        __syncthreads();
        uint32_t aA = sbase + (uint32_t)s * kStage;
        uint32_t aB = aA + 16384u;
        #pragma unroll
        for (int k16 = 0; k16 < 4; k16++) {
            int kb = k16 * 32;
            uint32_t af[2][4];
            #pragma unroll
            for (int mt = 0; mt < 2; mt++) {
                int row = aRow0 + mt * 16;
                uint32_t ad = aA + row * 128 + ((kb + aKofs) ^ ((row & 7) << 4));
                asm volatile("ldmatrix.sync.aligned.m8n8.x4.shared.b16 {%0,%1,%2,%3}, [%4];"
                             : "=r"(af[mt][0]), "=r"(af[mt][1]), "=r"(af[mt][2]), "=r"(af[mt][3])
                             : "r"(ad));
            }
            uint32_t bf[4][4];
            #pragma unroll
            for (int nt = 0; nt < 4; nt++) {
                int row = bRow0 + nt * 16;
                uint32_t bd = aB + row * 128 + ((kb + bKofs) ^ ((row & 7) << 4));
                asm volatile("ldmatrix.sync.aligned.m8n8.x4.shared.b16 {%0,%1,%2,%3}, [%4];"
                             : "=r"(bf[nt][0]), "=r"(bf[nt][1]), "=r"(bf[nt][2]), "=r"(bf[nt][3])
                             : "r"(bd));
            }
            #pragma unroll
            for (int mt = 0; mt < 2; mt++)
                #pragma unroll
                for (int n8 = 0; n8 < 8; n8++) {
                    uint32_t b0 = bf[n8 >> 1][(n8 & 1) * 2 + 0];
                    uint32_t b1 = bf[n8 >> 1][(n8 & 1) * 2 + 1];
                    asm volatile(
                        "mma.sync.aligned.m16n8k16.row.col.f32.f16.f16.f32 "
                        "{%0,%1,%2,%3}, {%4,%5,%6,%7}, {%8,%9}, {%0,%1,%2,%3};"
                        : "+f"(acc[mt][n8][0]), "+f"(acc[mt][n8][1]),
                          "+f"(acc[mt][n8][2]), "+f"(acc[mt][n8][3])
                        : "r"(af[mt][0]), "r"(af[mt][1]), "r"(af[mt][2]), "r"(af[mt][3]),
                          "r"(b0), "r"(b1));
                }
        }
        __syncthreads();
    }

    int g = lane >> 2, tig = lane & 3;
    #pragma unroll
    for (int mt = 0; mt < 2; mt++) {
        #pragma unroll
        for (int half = 0; half < 2; half++) {
            int gm = bm + wm * 32 + mt * 16 + g + half * 8;
            if (gm < 4160) {
                float* dst = (gm < 4096)
                    ? n_out + (size_t)gm * kO
                    : x_out + (size_t)(gm - 4096) * kO;
                #pragma unroll
                for (int n8 = 0; n8 < 8; n8++) {
                    int col = bn + wn * 64 + n8 * 8 + tig * 2;
                    float2 v = half ? make_float2(acc[mt][n8][2], acc[mt][n8][3])
                                    : make_float2(acc[mt][n8][0], acc[mt][n8][1]);
                    *(float2*)(dst + col) = v;
                }
            }
        }
    }
}

// ---------------------------------------------------------------------------
extern "C" void kernel_launch(void* const* d_in, const int* in_sizes, int n_in,
                              void* d_out, int out_size) {
    const float* x  = (const float*)d_in[0];
    const float* nb = (const float*)d_in[1];
    const float* W1 = (const float*)d_in[2];
    const float* W2 = (const float*)d_in[3];
    const float* Wc = (const float*)d_in[4];
    float* out = (float*)d_out;
    float* x_out = out;                          // (B, OC, OF)
    float* n_out = out + (size_t)kB * kO;        // (B, N, OC, OF)

    cudaFuncSetAttribute(k_zn_mma, cudaFuncAttributeMaxDynamicSharedMemorySize, kSmemZn);
    cudaFuncSetAttribute(k_mma2, cudaFuncAttributeMaxDynamicSharedMemorySize, kSmemG);

    k_wsum<<<1, 256>>>(W1, W2);
    k_s1<<<kB, 256>>>(x);
    k_w<<<kBN, 256>>>(nb);
    k_t<<<kB * kC, 256>>>(nb);
    k_adj<<<dim3(16, kB), 256>>>(x);
    k_zx<<<kB * kC * 32, 256>>>(x);
    k_zn_mma<<<kB * kC, 256, kSmemZn>>>(nb);
    k_wconv<<<kO, 256>>>(Wc);
    k_mma2<<<dim3(16, 33), 256, kSmemG>>>(x_out, n_out);
}

// round 9
// speedup vs baseline: 6.2790x; 1.6920x over previous
#include <cuda_runtime.h>
#include <cuda_fp16.h>
#include <cstdint>
#include <cstddef>

// Problem constants
namespace {
constexpr int kB  = 64;
constexpr int kN  = 64;
constexpr int kC  = 8;
constexpr int kF  = 256;
constexpr int kO  = 2048;   // OC*OF
constexpr int kCF = 2048;   // C*F
constexpr int kBN = 4096;   // B*N
constexpr int kMp = 4224;   // 4096 zn + 64 zx + 64 pad
}

// Scratch (device globals; no allocation allowed)
__device__ float g_w1sum[kF];
__device__ float g_w2sum[kF];
__device__ float g_s1[kB];
__device__ float g_w[kBN];
__device__ float g_t[kB * kCF];
__device__ __half g_adjh[(size_t)kB * kC * kF * kF];   // 67 MB: [b][c][a][d] fp16 hi
__device__ __half g_A2h[(size_t)kMp * kCF];            // 17.3 MB: zn|zx fp16
__device__ __half g_B2h[(size_t)kO * kCF];             // 8.4 MB: Wc fp16

// ---------------------------------------------------------------------------
// MUFU helpers (sqrt.approx / rcp.approx: ~8us for 33.5M on chip)
// ---------------------------------------------------------------------------
__device__ __forceinline__ float asqrt(float x) {
    float r; asm("sqrt.approx.f32 %0, %1;" : "=f"(r) : "f"(x)); return r;
}
__device__ __forceinline__ float arcp(float x) {
    float r; asm("rcp.approx.f32 %0, %1;" : "=f"(r) : "f"(x)); return r;
}
__device__ __forceinline__ float sgnroot(float a) {
    float s = asqrt(fmaxf(fabsf(a), 1e-8f));
    return (a == 0.0f) ? 0.0f : copysignf(s, a);
}

__device__ __forceinline__ float block_reduce_256(float v) {
    __shared__ float sh[8];
    int lane = threadIdx.x & 31, w = threadIdx.x >> 5;
    #pragma unroll
    for (int o = 16; o; o >>= 1) v += __shfl_xor_sync(0xffffffffu, v, o);
    if (lane == 0) sh[w] = v;
    __syncthreads();
    v = (threadIdx.x < 8) ? sh[threadIdx.x] : 0.0f;
    if (w == 0) {
        #pragma unroll
        for (int o = 4; o; o >>= 1) v += __shfl_xor_sync(0xffffffffu, v, o);
    }
    return v;
}

__device__ __forceinline__ uint32_t s2u(const void* p) {
    uint32_t a;
    asm("{ .reg .u64 t; cvta.to.shared.u64 t, %1; cvt.u32.u64 %0, t; }" : "=r"(a) : "l"(p));
    return a;
}

__device__ __forceinline__ uint32_t pack_h2(float a, float b) {
    __half ha = __float2half_rn(a), hb = __float2half_rn(b);
    return (uint32_t)__half_as_ushort(ha) | ((uint32_t)__half_as_ushort(hb) << 16);
}

// ---------------------------------------------------------------------------
// K0: column sums of W1 / W2
// ---------------------------------------------------------------------------
__global__ void k_wsum(const float* __restrict__ W1, const float* __restrict__ W2) {
    int f = threadIdx.x;
    float s1 = 0.f, s2 = 0.f;
    #pragma unroll
    for (int c = 0; c < kC; c++) {
        s1 += W1[c * kF + f];
        s2 += W2[c * kF + f];
    }
    g_w1sum[f] = s1;
    g_w2sum[f] = s2;
}

// K1: s1[b]
__global__ void k_s1(const float* __restrict__ x) {
    int b = blockIdx.x;
    float acc = 0.f;
    const float* p = x + (size_t)b * kCF;
    for (int i = threadIdx.x; i < kCF; i += 256)
        acc = fmaf(p[i], g_w1sum[i & (kF - 1)], acc);
    acc = block_reduce_256(acc);
    if (threadIdx.x == 0) g_s1[b] = acc;
}

// K2: w[b,n]
__global__ void k_w(const float* __restrict__ nb) {
    int bn = blockIdx.x;
    float acc = 0.f;
    const float* p = nb + (size_t)bn * kCF;
    for (int i = threadIdx.x; i < kCF; i += 256)
        acc = fmaf(p[i], g_w2sum[i & (kF - 1)], acc);
    acc = block_reduce_256(acc);
    if (threadIdx.x == 0) g_w[bn] = g_s1[bn >> 6] * acc;
}

// K3: t[b,c,f]
__global__ void k_t(const float* __restrict__ nb) {
    int bc = blockIdx.x;
    int b = bc >> 3, c = bc & 7;
    __shared__ float ws[kN];
    if (threadIdx.x < kN) ws[threadIdx.x] = g_w[b * kN + threadIdx.x];
    __syncthreads();
    int f = threadIdx.x;
    const float* p = nb + ((size_t)b * kN) * kCF + c * kF + f;
    float acc = 0.f;
    #pragma unroll 8
    for (int n = 0; n < kN; n++) acc = fmaf(ws[n], p[(size_t)n * kCF], acc);
    g_t[(size_t)bc * kF + f] = acc;
}

// ---------------------------------------------------------------------------
// K4: adj -> g_adjh fp16 (hi only)   [b][c][a][d]
// ---------------------------------------------------------------------------
__global__ void __launch_bounds__(256) k_adj(const float* __restrict__ x) {
    int b = blockIdx.y;
    int at = blockIdx.x;
    __shared__ float xs[kCF];
    __shared__ float ts[kCF];
    for (int i = threadIdx.x; i < kCF; i += 256) {
        xs[i] = x[(size_t)b * kCF + i];
        ts[i] = g_t[(size_t)b * kCF + i];
    }
    __syncthreads();
    int d = threadIdx.x;
    float xd[kC], td[kC];
    #pragma unroll
    for (int c = 0; c < kC; c++) { xd[c] = xs[c * kF + d]; td[c] = ts[c * kF + d]; }

    for (int ai = 0; ai < 16; ai++) {
        int a = at * 16 + ai;
        float v[kC];
        float norm = 0.f;
        #pragma unroll
        for (int c = 0; c < kC; c++) {
            float va = xs[c * kF + a] * td[c] + xd[c] * ts[c * kF + a];
            float sv = sgnroot(va);
            v[c] = sv;
            norm += fabsf(sv);
        }
        float inv = arcp(norm + 1e-7f);
        #pragma unroll
        for (int c = 0; c < kC; c++)
            g_adjh[((size_t)(b * kC + c) * kF + a) * kF + d] = __float2half_rn(v[c] * inv);
    }
}

// ---------------------------------------------------------------------------
// K5: zx -> g_A2h rows [4096, 4160)
// ---------------------------------------------------------------------------
__global__ void k_zx(const float* __restrict__ x) {
    int blk = blockIdx.x;
    int a8 = blk & 31, bc = blk >> 5;
    int warp = threadIdx.x >> 5, lane = threadIdx.x & 31;
    int a = a8 * 8 + warp;
    const __half* adjrow = g_adjh + ((size_t)bc * kF + a) * kF;
    const float* xr = x + (size_t)bc * kF;
    float acc = 0.f;
    #pragma unroll
    for (int d = lane; d < kF; d += 32)
        acc = fmaf(__half2float(adjrow[d]), xr[d], acc);
    #pragma unroll
    for (int o = 16; o; o >>= 1) acc += __shfl_xor_sync(0xffffffffu, acc, o);
    if (lane == 0) {
        int b = bc >> 3, c = bc & 7;
        g_A2h[(size_t)(4096 + b) * kCF + c * kF + a] = __float2half_rn(acc);
    }
}

// ---------------------------------------------------------------------------
// K6: zn via HMMA: per (b,c)  C[64 n x 256 a] = NB[64 x 256 d] @ ADJ[256 a x 256 d]^T
// 2-term exact-A: (nh + nl) . ah ; adj chunk loaded once, B-frags shared.
// smem: NB 8 chunks x 8KB (nh c0..3 | nl c0..3) = 64 KB, ADJ 2 x 32 KB stages.
// ---------------------------------------------------------------------------
namespace {
constexpr uint32_t kNbRegion = 65536;
constexpr uint32_t kAdjStage = 32768;
constexpr uint32_t kSmemZn   = kNbRegion + 2 * kAdjStage;  // 128 KB
}

__global__ void __launch_bounds__(256) k_zn_mma(const float* __restrict__ nb) {
    extern __shared__ char sm[];
    int tid = threadIdx.x, lane = tid & 31, wid = tid >> 5;
    int wm = wid >> 2, wn = wid & 3;             // 2(m) x 4(n); warp tile 32x64
    int bc = blockIdx.x;
    int b = bc >> 3, c = bc & 7;
    uint32_t sb = s2u(sm);
    uint32_t nbB = sb, adjB = sb + kNbRegion;

    const char* adj_bc = (const char*)(g_adjh + (size_t)bc * kF * kF);  // row 512 B
    const float* nb_bc = nb + ((size_t)b * kN) * kCF + c * kF;

    // load adj d-chunk q (64 d = 128 B per a-row) into stage q&1
    auto stage_load = [&](int q) {
        int srcoff = q * 128;
        uint32_t base = adjB + (uint32_t)(q & 1) * kAdjStage;
        #pragma unroll
        for (int k = 0; k < 8; k++) {
            int u = tid + (k << 8);          // 2048 quads: 256 rows x 8
            int row = u >> 3, q8 = u & 7;
            const char* g = adj_bc + (size_t)row * 512 + srcoff + q8 * 16;
            uint32_t so = base + (uint32_t)(row * 128) + (uint32_t)((q8 * 16) ^ ((row & 7) << 4));
            asm volatile("cp.async.cg.shared.global [%0], [%1], 16;" :: "r"(so), "l"(g));
        }
        asm volatile("cp.async.commit_group;");
    };

    stage_load(0);

    // NB load + fp16 hi/lo split into smem chunks (overlaps first adj load)
    #pragma unroll
    for (int itc = 0; itc < 8; itc++) {
        int e = tid + (itc << 8);            // 2048 groups: 64 rows x 32 (8 d each)
        int row = e >> 5, d0 = (e & 31) << 3;
        float4 v0 = *(const float4*)(nb_bc + (size_t)row * kCF + d0);
        float4 v1 = *(const float4*)(nb_bc + (size_t)row * kCF + d0 + 4);
        float v[8] = {v0.x, v0.y, v0.z, v0.w, v1.x, v1.y, v1.z, v1.w};
        uint32_t hw[4], lw[4];
        #pragma unroll
        for (int j = 0; j < 4; j++) {
            float a0 = v[2 * j], a1 = v[2 * j + 1];
            __half h0 = __float2half_rn(a0), h1 = __float2half_rn(a1);
            float r0 = a0 - __half2float(h0), r1 = a1 - __half2float(h1);
            hw[j] = (uint32_t)__half_as_ushort(h0) | ((uint32_t)__half_as_ushort(h1) << 16);
            lw[j] = pack_h2(r0, r1);
        }
        int chunk = d0 >> 6, cw = d0 & 63;
        uint32_t off = (uint32_t)(chunk * 8192 + row * 128) + (uint32_t)((cw * 2) ^ ((row & 7) << 4));
        *(uint4*)(sm + off)         = make_uint4(hw[0], hw[1], hw[2], hw[3]);
        *(uint4*)(sm + 32768 + off) = make_uint4(lw[0], lw[1], lw[2], lw[3]);
    }

    float acc[2][8][4];
    #pragma unroll
    for (int i = 0; i < 2; i++)
        #pragma unroll
        for (int j = 0; j < 8; j++)
            #pragma unroll
            for (int r = 0; r < 4; r++) acc[i][j][r] = 0.f;

    int aRow0 = wm * 32 + (lane & 15);
    int aKofs = (lane >> 4) << 4;
    int bRow0 = wn * 64 + (lane & 7) + ((lane & 16) >> 1);
    int bKofs = (lane & 8) << 1;

    const int NIT = 4;   // 4 d-chunks of 64
    for (int it = 0; it < NIT; it++) {
        if (it + 1 < NIT) {
            stage_load(it + 1);
            asm volatile("cp.async.wait_group 1;");
        } else {
            asm volatile("cp.async.wait_group 0;");
        }
        __syncthreads();
        uint32_t aH = nbB + (uint32_t)it * 8192u;           // nh chunk
        uint32_t aL = aH + 32768u;                           // nl chunk
        uint32_t bBase = adjB + (uint32_t)(it & 1) * kAdjStage;
        #pragma unroll
        for (int k16 = 0; k16 < 4; k16++) {
            int kb = k16 * 32;
            uint32_t afH[2][4], afL[2][4];
            #pragma unroll
            for (int mt = 0; mt < 2; mt++) {
                int row = aRow0 + mt * 16;
                uint32_t sw = ((kb + aKofs) ^ ((row & 7) << 4)) + row * 128;
                asm volatile("ldmatrix.sync.aligned.m8n8.x4.shared.b16 {%0,%1,%2,%3}, [%4];"
                             : "=r"(afH[mt][0]), "=r"(afH[mt][1]), "=r"(afH[mt][2]), "=r"(afH[mt][3])
                             : "r"(aH + sw));
                asm volatile("ldmatrix.sync.aligned.m8n8.x4.shared.b16 {%0,%1,%2,%3}, [%4];"
                             : "=r"(afL[mt][0]), "=r"(afL[mt][1]), "=r"(afL[mt][2]), "=r"(afL[mt][3])
                             : "r"(aL + sw));
            }
            uint32_t bf[4][4];
            #pragma unroll
            for (int nt = 0; nt < 4; nt++) {
                int row = bRow0 + nt * 16;
                uint32_t bd = bBase + row * 128 + ((kb + bKofs) ^ ((row & 7) << 4));
                asm volatile("ldmatrix.sync.aligned.m8n8.x4.shared.b16 {%0,%1,%2,%3}, [%4];"
                             : "=r"(bf[nt][0]), "=r"(bf[nt][1]), "=r"(bf[nt][2]), "=r"(bf[nt][3])
                             : "r"(bd));
            }
            #pragma unroll
            for (int mt = 0; mt < 2; mt++)
                #pragma unroll
                for (int n8 = 0; n8 < 8; n8++) {
                    uint32_t b0 = bf[n8 >> 1][(n8 & 1) * 2 + 0];
                    uint32_t b1 = bf[n8 >> 1][(n8 & 1) * 2 + 1];
                    asm volatile(
                        "mma.sync.aligned.m16n8k16.row.col.f32.f16.f16.f32 "
                        "{%0,%1,%2,%3}, {%4,%5,%6,%7}, {%8,%9}, {%0,%1,%2,%3};"
                        : "+f"(acc[mt][n8][0]), "+f"(acc[mt][n8][1]),
                          "+f"(acc[mt][n8][2]), "+f"(acc[mt][n8][3])
                        : "r"(afH[mt][0]), "r"(afH[mt][1]), "r"(afH[mt][2]), "r"(afH[mt][3]),
                          "r"(b0), "r"(b1));
                    asm volatile(
                        "mma.sync.aligned.m16n8k16.row.col.f32.f16.f16.f32 "
                        "{%0,%1,%2,%3}, {%4,%5,%6,%7}, {%8,%9}, {%0,%1,%2,%3};"
                        : "+f"(acc[mt][n8][0]), "+f"(acc[mt][n8][1]),
                          "+f"(acc[mt][n8][2]), "+f"(acc[mt][n8][3])
                        : "r"(afL[mt][0]), "r"(afL[mt][1]), "r"(afL[mt][2]), "r"(afL[mt][3]),
                          "r"(b0), "r"(b1));
                }
        }
        __syncthreads();
    }

    // epilogue: fp16 store into g_A2h rows b*64 + n, cols c*256 + a
    int g = lane >> 2, tig = lane & 3;
    #pragma unroll
    for (int mt = 0; mt < 2; mt++) {
        #pragma unroll
        for (int half = 0; half < 2; half++) {
            int lr = wm * 32 + mt * 16 + g + half * 8;
            __half* dst = g_A2h + (size_t)(b * kN + lr) * kCF + c * kF;
            #pragma unroll
            for (int n8 = 0; n8 < 8; n8++) {
                int col = wn * 64 + n8 * 8 + tig * 2;
                *(__half2*)(dst + col) =
                    __halves2half2(__float2half_rn(acc[mt][n8][half * 2]),
                                   __float2half_rn(acc[mt][n8][half * 2 + 1]));
            }
        }
    }
}

// ---------------------------------------------------------------------------
// K7: Wc -> g_B2h fp16
// ---------------------------------------------------------------------------
__global__ void k_wconv(const float* __restrict__ Wc) {
    int o = blockIdx.x;
    __half* rowb = g_B2h + (size_t)o * kCF;
    const float* src = Wc + (size_t)o * kCF;
    for (int j = threadIdx.x; j < kCF; j += 256)
        rowb[j] = __float2half_rn(src[j]);
}

// ---------------------------------------------------------------------------
// K8: single-term fp16 NT GEMM: C[4224,2048] = A2h @ B2h^T, K=2048
// CTA 128x128, 8 warps 4x2, double-buffered cp.async, NIT=32.
// ---------------------------------------------------------------------------
namespace {
constexpr uint32_t kStage = 32768;   // A 16K + B 16K
constexpr uint32_t kSmemG = 2 * kStage;
}

__global__ void __launch_bounds__(256) k_mma2(float* __restrict__ x_out,
                                              float* __restrict__ n_out) {
    extern __shared__ char sm[];
    int tid = threadIdx.x, lane = tid & 31, wid = tid >> 5;
    int wm = wid >> 1, wn = wid & 1;             // 4(m) x 2(n)
    int bm = blockIdx.y * 128, bn = blockIdx.x * 128;
    uint32_t sbase = s2u(sm);

    const char* Ag = (const char*)(g_A2h + (size_t)bm * kCF);   // row 4096 B
    const char* Bg = (const char*)(g_B2h + (size_t)bn * kCF);   // row 4096 B

    auto stage_load = [&](int it) {
        int koff = it * 128;                     // 64 halves
        uint32_t base = sbase + (uint32_t)(it & 1) * kStage;
        #pragma unroll
        for (int k = 0; k < 8; k++) {
            int u = tid + (k << 8);
            int isB = u >> 10;
            int v = u & 1023;
            int row = v >> 3, q8 = v & 7;
            const char* g = (isB ? Bg : Ag) + (size_t)row * 4096 + koff + q8 * 16;
            uint32_t so = base + (uint32_t)isB * 16384u + (uint32_t)(row * 128)
                          + (uint32_t)((q8 * 16) ^ ((row & 7) << 4));
            asm volatile("cp.async.cg.shared.global [%0], [%1], 16;" :: "r"(so), "l"(g));
        }
        asm volatile("cp.async.commit_group;");
    };

    float acc[2][8][4];
    #pragma unroll
    for (int i = 0; i < 2; i++)
        #pragma unroll
        for (int j = 0; j < 8; j++)
            #pragma unroll
            for (int r = 0; r < 4; r++) acc[i][j][r] = 0.f;

    int aRow0 = wm * 32 + (lane & 15);
    int aKofs = (lane >> 4) << 4;
    int bRow0 = wn * 64 + (lane & 7) + ((lane & 16) >> 1);
    int bKofs = (lane & 8) << 1;

    stage_load(0);
    const int NIT = 32;
    for (int it = 0; it < NIT; it++) {
        int s = it & 1;
        if (it + 1 < NIT) {
            stage_load(it + 1);
            asm volatile("cp.async.wait_group 1;");
        } else {
            asm volatile("cp.async.wait_group 0;");
        }
        __syncthreads();
        uint32_t aA = sbase + (uint32_t)s * kStage;
        uint32_t aB = aA + 16384u;
        #pragma unroll
        for (int k16 = 0; k16 < 4; k16++) {
            int kb = k16 * 32;
            uint32_t af[2][4];
            #pragma unroll
            for (int mt = 0; mt < 2; mt++) {
                int row = aRow0 + mt * 16;
                uint32_t ad = aA + row * 128 + ((kb + aKofs) ^ ((row & 7) << 4));
                asm volatile("ldmatrix.sync.aligned.m8n8.x4.shared.b16 {%0,%1,%2,%3}, [%4];"
                             : "=r"(af[mt][0]), "=r"(af[mt][1]), "=r"(af[mt][2]), "=r"(af[mt][3])
                             : "r"(ad));
            }
            uint32_t bf[4][4];
            #pragma unroll
            for (int nt = 0; nt < 4; nt++) {
                int row = bRow0 + nt * 16;
                uint32_t bd = aB + row * 128 + ((kb + bKofs) ^ ((row & 7) << 4));
                asm volatile("ldmatrix.sync.aligned.m8n8.x4.shared.b16 {%0,%1,%2,%3}, [%4];"
                             : "=r"(bf[nt][0]), "=r"(bf[nt][1]), "=r"(bf[nt][2]), "=r"(bf[nt][3])
                             : "r"(bd));
            }
            #pragma unroll
            for (int mt = 0; mt < 2; mt++)
                #pragma unroll
                for (int n8 = 0; n8 < 8; n8++) {
                    uint32_t b0 = bf[n8 >> 1][(n8 & 1) * 2 + 0];
                    uint32_t b1 = bf[n8 >> 1][(n8 & 1) * 2 + 1];
                    asm volatile(
                        "mma.sync.aligned.m16n8k16.row.col.f32.f16.f16.f32 "
                        "{%0,%1,%2,%3}, {%4,%5,%6,%7}, {%8,%9}, {%0,%1,%2,%3};"
                        : "+f"(acc[mt][n8][0]), "+f"(acc[mt][n8][1]),
                          "+f"(acc[mt][n8][2]), "+f"(acc[mt][n8][3])
                        : "r"(af[mt][0]), "r"(af[mt][1]), "r"(af[mt][2]), "r"(af[mt][3]),
                          "r"(b0), "r"(b1));
                }
        }
        __syncthreads();
    }

    int g = lane >> 2, tig = lane & 3;
    #pragma unroll
    for (int mt = 0; mt < 2; mt++) {
        #pragma unroll
        for (int half = 0; half < 2; half++) {
            int gm = bm + wm * 32 + mt * 16 + g + half * 8;
            if (gm < 4160) {
                float* dst = (gm < 4096)
                    ? n_out + (size_t)gm * kO
                    : x_out + (size_t)(gm - 4096) * kO;
                #pragma unroll
                for (int n8 = 0; n8 < 8; n8++) {
                    int col = bn + wn * 64 + n8 * 8 + tig * 2;
                    float2 v = half ? make_float2(acc[mt][n8][2], acc[mt][n8][3])
                                    : make_float2(acc[mt][n8][0], acc[mt][n8][1]);
                    *(float2*)(dst + col) = v;
                }
            }
        }
    }
}

// ---------------------------------------------------------------------------
extern "C" void kernel_launch(void* const* d_in, const int* in_sizes, int n_in,
                              void* d_out, int out_size) {
    const float* x  = (const float*)d_in[0];
    const float* nb = (const float*)d_in[1];
    const float* W1 = (const float*)d_in[2];
    const float* W2 = (const float*)d_in[3];
    const float* Wc = (const float*)d_in[4];
    float* out = (float*)d_out;
    float* x_out = out;                          // (B, OC, OF)
    float* n_out = out + (size_t)kB * kO;        // (B, N, OC, OF)

    cudaFuncSetAttribute(k_zn_mma, cudaFuncAttributeMaxDynamicSharedMemorySize, kSmemZn);
    cudaFuncSetAttribute(k_mma2, cudaFuncAttributeMaxDynamicSharedMemorySize, kSmemG);

    k_wsum<<<1, 256>>>(W1, W2);
    k_s1<<<kB, 256>>>(x);
    k_w<<<kBN, 256>>>(nb);
    k_t<<<kB * kC, 256>>>(nb);
    k_adj<<<dim3(16, kB), 256>>>(x);
    k_zx<<<kB * kC * 32, 256>>>(x);
    k_zn_mma<<<kB * kC, 256, kSmemZn>>>(nb);
    k_wconv<<<kO, 256>>>(Wc);
    k_mma2<<<dim3(16, 33), 256, kSmemG>>>(x_out, n_out);
}

// round 10
// speedup vs baseline: 6.7812x; 1.0800x over previous
#include <cuda_runtime.h>
#include <cuda_fp16.h>
#include <cstdint>
#include <cstddef>

// Problem constants
namespace {
constexpr int kB  = 64;
constexpr int kN  = 64;
constexpr int kC  = 8;
constexpr int kF  = 256;
constexpr int kO  = 2048;   // OC*OF
constexpr int kCF = 2048;   // C*F
constexpr int kBN = 4096;   // B*N
constexpr int kMp = 4224;   // 4096 zn + 64 zx + 64 pad
}

// Scratch (device globals; no allocation allowed)
__device__ float g_w1sum[kF];
__device__ float g_w2sum[kF];
__device__ float g_s1[kB];
__device__ float g_w[kBN];
__device__ float g_t[kB * kCF];
__device__ __half g_adjh[(size_t)kB * kC * kF * kF];   // 67 MB: [b][c][a][d] fp16 hi
__device__ __half g_A2h[(size_t)kMp * kCF];            // 17.3 MB: zn|zx fp16
__device__ __half g_B2h[(size_t)kO * kCF];             // 8.4 MB: Wc fp16

// ---------------------------------------------------------------------------
// MUFU helpers
// ---------------------------------------------------------------------------
__device__ __forceinline__ float asqrt(float x) {
    float r; asm("sqrt.approx.f32 %0, %1;" : "=f"(r) : "f"(x)); return r;
}
__device__ __forceinline__ float arcp(float x) {
    float r; asm("rcp.approx.f32 %0, %1;" : "=f"(r) : "f"(x)); return r;
}
__device__ __forceinline__ float sgnroot(float a) {
    float s = asqrt(fmaxf(fabsf(a), 1e-8f));
    return (a == 0.0f) ? 0.0f : copysignf(s, a);
}

__device__ __forceinline__ float block_reduce_256(float v) {
    __shared__ float sh[8];
    int lane = threadIdx.x & 31, w = threadIdx.x >> 5;
    #pragma unroll
    for (int o = 16; o; o >>= 1) v += __shfl_xor_sync(0xffffffffu, v, o);
    if (lane == 0) sh[w] = v;
    __syncthreads();
    v = (threadIdx.x < 8) ? sh[threadIdx.x] : 0.0f;
    if (w == 0) {
        #pragma unroll
        for (int o = 4; o; o >>= 1) v += __shfl_xor_sync(0xffffffffu, v, o);
    }
    return v;
}

__device__ __forceinline__ uint32_t s2u(const void* p) {
    uint32_t a;
    asm("{ .reg .u64 t; cvta.to.shared.u64 t, %1; cvt.u32.u64 %0, t; }" : "=r"(a) : "l"(p));
    return a;
}

// ---------------------------------------------------------------------------
// K0: column sums of W1 / W2
// ---------------------------------------------------------------------------
__global__ void k_wsum(const float* __restrict__ W1, const float* __restrict__ W2) {
    int f = threadIdx.x;
    float s1 = 0.f, s2 = 0.f;
    #pragma unroll
    for (int c = 0; c < kC; c++) {
        s1 += W1[c * kF + f];
        s2 += W2[c * kF + f];
    }
    g_w1sum[f] = s1;
    g_w2sum[f] = s2;
}

// K1: s1[b]
__global__ void k_s1(const float* __restrict__ x) {
    int b = blockIdx.x;
    float acc = 0.f;
    const float* p = x + (size_t)b * kCF;
    for (int i = threadIdx.x; i < kCF; i += 256)
        acc = fmaf(p[i], g_w1sum[i & (kF - 1)], acc);
    acc = block_reduce_256(acc);
    if (threadIdx.x == 0) g_s1[b] = acc;
}

// K2: w[b,n]
__global__ void k_w(const float* __restrict__ nb) {
    int bn = blockIdx.x;
    float acc = 0.f;
    const float* p = nb + (size_t)bn * kCF;
    for (int i = threadIdx.x; i < kCF; i += 256)
        acc = fmaf(p[i], g_w2sum[i & (kF - 1)], acc);
    acc = block_reduce_256(acc);
    if (threadIdx.x == 0) g_w[bn] = g_s1[bn >> 6] * acc;
}

// K3: t[b,c,f]
__global__ void k_t(const float* __restrict__ nb) {
    int bc = blockIdx.x;
    int b = bc >> 3, c = bc & 7;
    __shared__ float ws[kN];
    if (threadIdx.x < kN) ws[threadIdx.x] = g_w[b * kN + threadIdx.x];
    __syncthreads();
    int f = threadIdx.x;
    const float* p = nb + ((size_t)b * kN) * kCF + c * kF + f;
    float acc = 0.f;
    #pragma unroll 8
    for (int n = 0; n < kN; n++) acc = fmaf(ws[n], p[(size_t)n * kCF], acc);
    g_t[(size_t)bc * kF + f] = acc;
}

// ---------------------------------------------------------------------------
// K4: adj -> g_adjh fp16 (hi only)   [b][c][a][d]
// ---------------------------------------------------------------------------
__global__ void __launch_bounds__(256) k_adj(const float* __restrict__ x) {
    int b = blockIdx.y;
    int at = blockIdx.x;
    __shared__ float xs[kCF];
    __shared__ float ts[kCF];
    for (int i = threadIdx.x; i < kCF; i += 256) {
        xs[i] = x[(size_t)b * kCF + i];
        ts[i] = g_t[(size_t)b * kCF + i];
    }
    __syncthreads();
    int d = threadIdx.x;
    float xd[kC], td[kC];
    #pragma unroll
    for (int c = 0; c < kC; c++) { xd[c] = xs[c * kF + d]; td[c] = ts[c * kF + d]; }

    for (int ai = 0; ai < 16; ai++) {
        int a = at * 16 + ai;
        float v[kC];
        float norm = 0.f;
        #pragma unroll
        for (int c = 0; c < kC; c++) {
            float va = xs[c * kF + a] * td[c] + xd[c] * ts[c * kF + a];
            float sv = sgnroot(va);
            v[c] = sv;
            norm += fabsf(sv);
        }
        float inv = arcp(norm + 1e-7f);
        #pragma unroll
        for (int c = 0; c < kC; c++)
            g_adjh[((size_t)(b * kC + c) * kF + a) * kF + d] = __float2half_rn(v[c] * inv);
    }
}

// ---------------------------------------------------------------------------
// K5: zx -> g_A2h rows [4096, 4160)
// ---------------------------------------------------------------------------
__global__ void k_zx(const float* __restrict__ x) {
    int blk = blockIdx.x;
    int a8 = blk & 31, bc = blk >> 5;
    int warp = threadIdx.x >> 5, lane = threadIdx.x & 31;
    int a = a8 * 8 + warp;
    const __half* adjrow = g_adjh + ((size_t)bc * kF + a) * kF;
    const float* xr = x + (size_t)bc * kF;
    float acc = 0.f;
    #pragma unroll
    for (int d = lane; d < kF; d += 32)
        acc = fmaf(__half2float(adjrow[d]), xr[d], acc);
    #pragma unroll
    for (int o = 16; o; o >>= 1) acc += __shfl_xor_sync(0xffffffffu, acc, o);
    if (lane == 0) {
        int b = bc >> 3, c = bc & 7;
        g_A2h[(size_t)(4096 + b) * kCF + c * kF + a] = __float2half_rn(acc);
    }
}

// ---------------------------------------------------------------------------
// K6: zn via HMMA: per (b,c)  C[64 n x 256 a] = NB[64 x 256 d] @ ADJ[256 a x 256 d]^T
// single-term fp16: nh . ah  (dropped nl term: +1.4e-4 incoherent error)
// smem: NB 4 chunks x 8KB = 32 KB, ADJ 2 x 32 KB stages.
// ---------------------------------------------------------------------------
namespace {
constexpr uint32_t kNbRegion = 32768;
constexpr uint32_t kAdjStage = 32768;
constexpr uint32_t kSmemZn   = kNbRegion + 2 * kAdjStage;  // 96 KB
}

__global__ void __launch_bounds__(256) k_zn_mma(const float* __restrict__ nb) {
    extern __shared__ char sm[];
    int tid = threadIdx.x, lane = tid & 31, wid = tid >> 5;
    int wm = wid >> 2, wn = wid & 3;             // 2(m) x 4(n); warp tile 32x64
    int bc = blockIdx.x;
    int b = bc >> 3, c = bc & 7;
    uint32_t sb = s2u(sm);
    uint32_t nbB = sb, adjB = sb + kNbRegion;

    const char* adj_bc = (const char*)(g_adjh + (size_t)bc * kF * kF);  // row 512 B
    const float* nb_bc = nb + ((size_t)b * kN) * kCF + c * kF;

    // load adj d-chunk q (64 d = 128 B per a-row) into stage q&1
    auto stage_load = [&](int q) {
        int srcoff = q * 128;
        uint32_t base = adjB + (uint32_t)(q & 1) * kAdjStage;
        #pragma unroll
        for (int k = 0; k < 8; k++) {
            int u = tid + (k << 8);          // 2048 quads: 256 rows x 8
            int row = u >> 3, q8 = u & 7;
            const char* g = adj_bc + (size_t)row * 512 + srcoff + q8 * 16;
            uint32_t so = base + (uint32_t)(row * 128) + (uint32_t)((q8 * 16) ^ ((row & 7) << 4));
            asm volatile("cp.async.cg.shared.global [%0], [%1], 16;" :: "r"(so), "l"(g));
        }
        asm volatile("cp.async.commit_group;");
    };

    stage_load(0);

    // NB load + fp16 convert into smem chunks (overlaps first adj load)
    #pragma unroll
    for (int itc = 0; itc < 8; itc++) {
        int e = tid + (itc << 8);            // 2048 groups: 64 rows x 32 (8 d each)
        int row = e >> 5, d0 = (e & 31) << 3;
        float4 v0 = *(const float4*)(nb_bc + (size_t)row * kCF + d0);
        float4 v1 = *(const float4*)(nb_bc + (size_t)row * kCF + d0 + 4);
        float v[8] = {v0.x, v0.y, v0.z, v0.w, v1.x, v1.y, v1.z, v1.w};
        uint32_t hw[4];
        #pragma unroll
        for (int j = 0; j < 4; j++) {
            __half h0 = __float2half_rn(v[2 * j]), h1 = __float2half_rn(v[2 * j + 1]);
            hw[j] = (uint32_t)__half_as_ushort(h0) | ((uint32_t)__half_as_ushort(h1) << 16);
        }
        int chunk = d0 >> 6, cw = d0 & 63;
        uint32_t off = (uint32_t)(chunk * 8192 + row * 128) + (uint32_t)((cw * 2) ^ ((row & 7) << 4));
        *(uint4*)(sm + off) = make_uint4(hw[0], hw[1], hw[2], hw[3]);
    }

    float acc[2][8][4];
    #pragma unroll
    for (int i = 0; i < 2; i++)
        #pragma unroll
        for (int j = 0; j < 8; j++)
            #pragma unroll
            for (int r = 0; r < 4; r++) acc[i][j][r] = 0.f;

    int aRow0 = wm * 32 + (lane & 15);
    int aKofs = (lane >> 4) << 4;
    int bRow0 = wn * 64 + (lane & 7) + ((lane & 16) >> 1);
    int bKofs = (lane & 8) << 1;

    const int NIT = 4;   // 4 d-chunks of 64
    for (int it = 0; it < NIT; it++) {
        if (it + 1 < NIT) {
            stage_load(it + 1);
            asm volatile("cp.async.wait_group 1;");
        } else {
            asm volatile("cp.async.wait_group 0;");
        }
        __syncthreads();
        uint32_t aH = nbB + (uint32_t)it * 8192u;           // nh chunk
        uint32_t bBase = adjB + (uint32_t)(it & 1) * kAdjStage;
        #pragma unroll
        for (int k16 = 0; k16 < 4; k16++) {
            int kb = k16 * 32;
            uint32_t af[2][4];
            #pragma unroll
            for (int mt = 0; mt < 2; mt++) {
                int row = aRow0 + mt * 16;
                uint32_t sw = ((kb + aKofs) ^ ((row & 7) << 4)) + row * 128;
                asm volatile("ldmatrix.sync.aligned.m8n8.x4.shared.b16 {%0,%1,%2,%3}, [%4];"
                             : "=r"(af[mt][0]), "=r"(af[mt][1]), "=r"(af[mt][2]), "=r"(af[mt][3])
                             : "r"(aH + sw));
            }
            uint32_t bf[4][4];
            #pragma unroll
            for (int nt = 0; nt < 4; nt++) {
                int row = bRow0 + nt * 16;
                uint32_t bd = bBase + row * 128 + ((kb + bKofs) ^ ((row & 7) << 4));
                asm volatile("ldmatrix.sync.aligned.m8n8.x4.shared.b16 {%0,%1,%2,%3}, [%4];"
                             : "=r"(bf[nt][0]), "=r"(bf[nt][1]), "=r"(bf[nt][2]), "=r"(bf[nt][3])
                             : "r"(bd));
            }
            #pragma unroll
            for (int mt = 0; mt < 2; mt++)
                #pragma unroll
                for (int n8 = 0; n8 < 8; n8++) {
                    uint32_t b0 = bf[n8 >> 1][(n8 & 1) * 2 + 0];
                    uint32_t b1 = bf[n8 >> 1][(n8 & 1) * 2 + 1];
                    asm volatile(
                        "mma.sync.aligned.m16n8k16.row.col.f32.f16.f16.f32 "
                        "{%0,%1,%2,%3}, {%4,%5,%6,%7}, {%8,%9}, {%0,%1,%2,%3};"
                        : "+f"(acc[mt][n8][0]), "+f"(acc[mt][n8][1]),
                          "+f"(acc[mt][n8][2]), "+f"(acc[mt][n8][3])
                        : "r"(af[mt][0]), "r"(af[mt][1]), "r"(af[mt][2]), "r"(af[mt][3]),
                          "r"(b0), "r"(b1));
                }
        }
        __syncthreads();
    }

    // epilogue: fp16 store into g_A2h rows b*64 + n, cols c*256 + a
    int g = lane >> 2, tig = lane & 3;
    #pragma unroll
    for (int mt = 0; mt < 2; mt++) {
        #pragma unroll
        for (int half = 0; half < 2; half++) {
            int lr = wm * 32 + mt * 16 + g + half * 8;
            __half* dst = g_A2h + (size_t)(b * kN + lr) * kCF + c * kF;
            #pragma unroll
            for (int n8 = 0; n8 < 8; n8++) {
                int col = wn * 64 + n8 * 8 + tig * 2;
                *(__half2*)(dst + col) =
                    __halves2half2(__float2half_rn(acc[mt][n8][half * 2]),
                                   __float2half_rn(acc[mt][n8][half * 2 + 1]));
            }
        }
    }
}

// ---------------------------------------------------------------------------
// K7: Wc -> g_B2h fp16
// ---------------------------------------------------------------------------
__global__ void k_wconv(const float* __restrict__ Wc) {
    int o = blockIdx.x;
    __half* rowb = g_B2h + (size_t)o * kCF;
    const float* src = Wc + (size_t)o * kCF;
    for (int j = threadIdx.x; j < kCF; j += 256)
        rowb[j] = __float2half_rn(src[j]);
}

// ---------------------------------------------------------------------------
// K8: single-term fp16 NT GEMM: C[4224,2048] = A2h @ B2h^T, K=2048
// CTA 128x128, 8 warps 4x2, double-buffered cp.async, NIT=32.
// ---------------------------------------------------------------------------
namespace {
constexpr uint32_t kStage = 32768;   // A 16K + B 16K
constexpr uint32_t kSmemG = 2 * kStage;
}

__global__ void __launch_bounds__(256) k_mma2(float* __restrict__ x_out,
                                              float* __restrict__ n_out) {
    extern __shared__ char sm[];
    int tid = threadIdx.x, lane = tid & 31, wid = tid >> 5;
    int wm = wid >> 1, wn = wid & 1;             // 4(m) x 2(n)
    int bm = blockIdx.y * 128, bn = blockIdx.x * 128;
    uint32_t sbase = s2u(sm);

    const char* Ag = (const char*)(g_A2h + (size_t)bm * kCF);   // row 4096 B
    const char* Bg = (const char*)(g_B2h + (size_t)bn * kCF);   // row 4096 B

    auto stage_load = [&](int it) {
        int koff = it * 128;                     // 64 halves
        uint32_t base = sbase + (uint32_t)(it & 1) * kStage;
        #pragma unroll
        for (int k = 0; k < 8; k++) {
            int u = tid + (k << 8);
            int isB = u >> 10;
            int v = u & 1023;
            int row = v >> 3, q8 = v & 7;
            const char* g = (isB ? Bg : Ag) + (size_t)row * 4096 + koff + q8 * 16;
            uint32_t so = base + (uint32_t)isB * 16384u + (uint32_t)(row * 128)
                          + (uint32_t)((q8 * 16) ^ ((row & 7) << 4));
            asm volatile("cp.async.cg.shared.global [%0], [%1], 16;" :: "r"(so), "l"(g));
        }
        asm volatile("cp.async.commit_group;");
    };

    float acc[2][8][4];
    #pragma unroll
    for (int i = 0; i < 2; i++)
        #pragma unroll
        for (int j = 0; j < 8; j++)
            #pragma unroll
            for (int r = 0; r < 4; r++) acc[i][j][r] = 0.f;

    int aRow0 = wm * 32 + (lane & 15);
    int aKofs = (lane >> 4) << 4;
    int bRow0 = wn * 64 + (lane & 7) + ((lane & 16) >> 1);
    int bKofs = (lane & 8) << 1;

    stage_load(0);
    const int NIT = 32;
    for (int it = 0; it < NIT; it++) {
        int s = it & 1;
        if (it + 1 < NIT) {
            stage_load(it + 1);
            asm volatile("cp.async.wait_group 1;");
        } else {
            asm volatile("cp.async.wait_group 0;");
        }
        __syncthreads();
        uint32_t aA = sbase + (uint32_t)s * kStage;
        uint32_t aB = aA + 16384u;
        #pragma unroll
        for (int k16 = 0; k16 < 4; k16++) {
            int kb = k16 * 32;
            uint32_t af[2][4];
            #pragma unroll
            for (int mt = 0; mt < 2; mt++) {
                int row = aRow0 + mt * 16;
                uint32_t ad = aA + row * 128 + ((kb + aKofs) ^ ((row & 7) << 4));
                asm volatile("ldmatrix.sync.aligned.m8n8.x4.shared.b16 {%0,%1,%2,%3}, [%4];"
                             : "=r"(af[mt][0]), "=r"(af[mt][1]), "=r"(af[mt][2]), "=r"(af[mt][3])
                             : "r"(ad));
            }
            uint32_t bf[4][4];
            #pragma unroll
            for (int nt = 0; nt < 4; nt++) {
                int row = bRow0 + nt * 16;
                uint32_t bd = aB + row * 128 + ((kb + bKofs) ^ ((row & 7) << 4));
                asm volatile("ldmatrix.sync.aligned.m8n8.x4.shared.b16 {%0,%1,%2,%3}, [%4];"
                             : "=r"(bf[nt][0]), "=r"(bf[nt][1]), "=r"(bf[nt][2]), "=r"(bf[nt][3])
                             : "r"(bd));
            }
            #pragma unroll
            for (int mt = 0; mt < 2; mt++)
                #pragma unroll
                for (int n8 = 0; n8 < 8; n8++) {
                    uint32_t b0 = bf[n8 >> 1][(n8 & 1) * 2 + 0];
                    uint32_t b1 = bf[n8 >> 1][(n8 & 1) * 2 + 1];
                    asm volatile(
                        "mma.sync.aligned.m16n8k16.row.col.f32.f16.f16.f32 "
                        "{%0,%1,%2,%3}, {%4,%5,%6,%7}, {%8,%9}, {%0,%1,%2,%3};"
                        : "+f"(acc[mt][n8][0]), "+f"(acc[mt][n8][1]),
                          "+f"(acc[mt][n8][2]), "+f"(acc[mt][n8][3])
                        : "r"(af[mt][0]), "r"(af[mt][1]), "r"(af[mt][2]), "r"(af[mt][3]),
                          "r"(b0), "r"(b1));
                }
        }
        __syncthreads();
    }

    int g = lane >> 2, tig = lane & 3;
    #pragma unroll
    for (int mt = 0; mt < 2; mt++) {
        #pragma unroll
        for (int half = 0; half < 2; half++) {
            int gm = bm + wm * 32 + mt * 16 + g + half * 8;
            if (gm < 4160) {
                float* dst = (gm < 4096)
                    ? n_out + (size_t)gm * kO
                    : x_out + (size_t)(gm - 4096) * kO;
                #pragma unroll
                for (int n8 = 0; n8 < 8; n8++) {
                    int col = bn + wn * 64 + n8 * 8 + tig * 2;
                    float2 v = half ? make_float2(acc[mt][n8][2], acc[mt][n8][3])
                                    : make_float2(acc[mt][n8][0], acc[mt][n8][1]);
                    *(float2*)(dst + col) = v;
                }
            }
        }
    }
}

// ---------------------------------------------------------------------------
extern "C" void kernel_launch(void* const* d_in, const int* in_sizes, int n_in,
                              void* d_out, int out_size) {
    const float* x  = (const float*)d_in[0];
    const float* nb = (const float*)d_in[1];
    const float* W1 = (const float*)d_in[2];
    const float* W2 = (const float*)d_in[3];
    const float* Wc = (const float*)d_in[4];
    float* out = (float*)d_out;
    float* x_out = out;                          // (B, OC, OF)
    float* n_out = out + (size_t)kB * kO;        // (B, N, OC, OF)

    cudaFuncSetAttribute(k_zn_mma, cudaFuncAttributeMaxDynamicSharedMemorySize, kSmemZn);
    cudaFuncSetAttribute(k_mma2, cudaFuncAttributeMaxDynamicSharedMemorySize, kSmemG);

    k_wsum<<<1, 256>>>(W1, W2);
    k_s1<<<kB, 256>>>(x);
    k_w<<<kBN, 256>>>(nb);
    k_t<<<kB * kC, 256>>>(nb);
    k_adj<<<dim3(16, kB), 256>>>(x);
    k_zx<<<kB * kC * 32, 256>>>(x);
    k_zn_mma<<<kB * kC, 256, kSmemZn>>>(nb);
    k_wconv<<<kO, 256>>>(Wc);
    k_mma2<<<dim3(16, 33), 256, kSmemG>>>(x_out, n_out);
}